// round 2
// baseline (speedup 1.0000x reference)
#include <cuda_runtime.h>
#include <float.h>

// Problem constants (fixed-shape problem)
#define NNODES 50000
#define IN_CH  256
#define HEADS  8
#define HID    32
#define C1     (HEADS*HID)   // 256
#define OUT_CH 64
#define NEG_SLOPE 0.2f

// ---------------- scratch (device globals; no allocation allowed) ----------
__device__ float g_h1  [NNODES*C1];      // x @ W1            [N,256]
__device__ float g_o1  [NNODES*C1];      // layer-1 aggregate [N,256]
__device__ float g_h2  [NNODES*OUT_CH];  // relu(o1) @ W2     [N,64]
__device__ float g_as1 [NNODES*HEADS];
__device__ float g_ad1 [NNODES*HEADS];
__device__ float g_m1  [NNODES*HEADS];
__device__ float g_den1[NNODES*HEADS];
__device__ float g_as2 [NNODES];
__device__ float g_ad2 [NNODES];
__device__ float g_m2  [NNODES];
__device__ float g_den2[NNODES];

// ---------------- small helpers -------------------------------------------
__global__ void fill_k(float* __restrict__ p, float v, int n) {
    int i = blockIdx.x * blockDim.x + threadIdx.x;
    if (i < n) p[i] = v;
}

__device__ __forceinline__ void atomicMaxF(float* addr, float val) {
    int old = __float_as_int(*addr);
    while (__int_as_float(old) < val) {
        int assumed = old;
        old = atomicCAS((int*)addr, assumed, __float_as_int(val));
        if (old == assumed) break;
    }
}

// ---------------- tiled SGEMM: C[M,N] = A[M,K] @ B[K,N] -------------------
// BM=64, BN=64, BK=16, 256 threads, 4x4 micro-tile. Requires K%16==0, N%64==0.
__global__ void gemm_tiled(const float* __restrict__ A, const float* __restrict__ B,
                           float* __restrict__ C, int M, int N, int K) {
    const int BM = 64, BN = 64, BK = 16;
    __shared__ float As[BK][BM + 4];
    __shared__ float Bs[BK][BN];

    int tid = threadIdx.x;
    int tx = tid & 15;       // 0..15
    int ty = tid >> 4;       // 0..15
    int row0 = blockIdx.y * BM;
    int col0 = blockIdx.x * BN;

    float acc[4][4] = {};

    for (int k0 = 0; k0 < K; k0 += BK) {
        // load A tile (64 rows x 16 k), transposed into As[k][m]
        {
            int m = tid >> 2;            // 0..63
            int k = (tid & 3) * 4;       // 0,4,8,12
            int gr = row0 + m;
            float4 v = make_float4(0.f, 0.f, 0.f, 0.f);
            if (gr < M)
                v = *reinterpret_cast<const float4*>(A + (size_t)gr * K + k0 + k);
            As[k + 0][m] = v.x; As[k + 1][m] = v.y;
            As[k + 2][m] = v.z; As[k + 3][m] = v.w;
        }
        // load B tile (16 k x 64 n), coalesced
        #pragma unroll
        for (int i = 0; i < 4; i++) {
            int idx = tid + i * 256;
            int k = idx >> 6;
            int nn = idx & 63;
            Bs[k][nn] = B[(size_t)(k0 + k) * N + col0 + nn];
        }
        __syncthreads();

        #pragma unroll
        for (int kk = 0; kk < BK; kk++) {
            float4 a4 = *reinterpret_cast<const float4*>(&As[kk][ty * 4]);
            float4 b4 = *reinterpret_cast<const float4*>(&Bs[kk][tx * 4]);
            float av[4] = {a4.x, a4.y, a4.z, a4.w};
            float bv[4] = {b4.x, b4.y, b4.z, b4.w};
            #pragma unroll
            for (int i = 0; i < 4; i++)
                #pragma unroll
                for (int j = 0; j < 4; j++)
                    acc[i][j] = fmaf(av[i], bv[j], acc[i][j]);
        }
        __syncthreads();
    }

    #pragma unroll
    for (int i = 0; i < 4; i++) {
        int gr = row0 + ty * 4 + i;
        if (gr < M) {
            float4 o = make_float4(acc[i][0], acc[i][1], acc[i][2], acc[i][3]);
            *reinterpret_cast<float4*>(C + (size_t)gr * N + col0 + tx * 4) = o;
        }
    }
}

// ---------------- attention coefficients ----------------------------------
__global__ void attn_coeff(const float* __restrict__ h,
                           const float* __restrict__ att_s,
                           const float* __restrict__ att_d,
                           float* __restrict__ as, float* __restrict__ ad,
                           int n, int heads, int F) {
    int i = blockIdx.x * blockDim.x + threadIdx.x;
    if (i >= n * heads) return;
    int node = i / heads, hh = i - node * heads;
    const float* row = h + (size_t)node * heads * F + hh * F;
    const float* ws = att_s + hh * F;
    const float* wd = att_d + hh * F;
    float s = 0.f, d = 0.f;
    #pragma unroll 8
    for (int f = 0; f < F; f++) {
        float v = row[f];
        s = fmaf(v, ws[f], s);
        d = fmaf(v, wd[f], d);
    }
    as[i] = s;
    ad[i] = d;
}

// ---------------- edge passes ----------------------------------------------
__global__ void edge_max_k(const int* __restrict__ src, const int* __restrict__ dst,
                           const float* __restrict__ as, const float* __restrict__ ad,
                           float* __restrict__ m, int Etot, int E_, int heads) {
    int i = blockIdx.x * blockDim.x + threadIdx.x;
    if (i >= Etot) return;
    int s, d;
    if (i < E_) { s = src[i]; d = dst[i]; }
    else        { s = d = i - E_; }
    for (int h = 0; h < heads; h++) {
        float e = as[s * heads + h] + ad[d * heads + h];
        e = e > 0.f ? e : NEG_SLOPE * e;
        atomicMaxF(&m[d * heads + h], e);
    }
}

__global__ void edge_sum_k(const int* __restrict__ src, const int* __restrict__ dst,
                           const float* __restrict__ as, const float* __restrict__ ad,
                           const float* __restrict__ m, float* __restrict__ den,
                           int Etot, int E_, int heads) {
    int i = blockIdx.x * blockDim.x + threadIdx.x;
    if (i >= Etot) return;
    int s, d;
    if (i < E_) { s = src[i]; d = dst[i]; }
    else        { s = d = i - E_; }
    for (int h = 0; h < heads; h++) {
        float e = as[s * heads + h] + ad[d * heads + h];
        e = e > 0.f ? e : NEG_SLOPE * e;
        atomicAdd(&den[d * heads + h], __expf(e - m[d * heads + h]));
    }
}

// scatter aggregation: out[d, :] += alpha * h[s, :]
template<int HF, int F, int H>
__global__ void aggregate_k(const int* __restrict__ src, const int* __restrict__ dst,
                            const float* __restrict__ as, const float* __restrict__ ad,
                            const float* __restrict__ m, const float* __restrict__ den,
                            const float* __restrict__ h, float* __restrict__ out,
                            int Etot, int E_) {
    const int EPB = 256 / HF;
    int e = blockIdx.x * EPB + threadIdx.x / HF;
    if (e >= Etot) return;
    int c = threadIdx.x % HF;
    int s, d;
    if (e < E_) { s = src[e]; d = dst[e]; }
    else        { s = d = e - E_; }
    int hh = c / F;
    float ev = as[s * H + hh] + ad[d * H + hh];
    ev = ev > 0.f ? ev : NEG_SLOPE * ev;
    float alpha = __expf(ev - m[d * H + hh]) / den[d * H + hh];
    atomicAdd(out + (size_t)d * HF + c, alpha * h[(size_t)s * HF + c]);
}

// ---------------- epilogues -------------------------------------------------
__global__ void relu_bias_k(float* __restrict__ p, const float* __restrict__ b, int n, int C) {
    int i = blockIdx.x * blockDim.x + threadIdx.x;
    if (i >= n) return;
    float v = p[i] + b[i % C];
    p[i] = v > 0.f ? v : 0.f;
}

__global__ void add_bias_k(float* __restrict__ p, const float* __restrict__ b, int n, int C) {
    int i = blockIdx.x * blockDim.x + threadIdx.x;
    if (i >= n) return;
    p[i] += b[i % C];
}

// ---------------- launch ----------------------------------------------------
extern "C" void kernel_launch(void* const* d_in, const int* in_sizes, int n_in,
                              void* d_out, int out_size) {
    const float* x      = (const float*)d_in[0];
    const int*   ei     = (const int*)d_in[1];     // edge_index delivered as int32
    const float* W1     = (const float*)d_in[2];
    const float* att_s1 = (const float*)d_in[3];
    const float* att_d1 = (const float*)d_in[4];
    const float* b1     = (const float*)d_in[5];
    const float* W2     = (const float*)d_in[6];
    const float* att_s2 = (const float*)d_in[7];
    const float* att_d2 = (const float*)d_in[8];
    const float* b2     = (const float*)d_in[9];
    float* out = (float*)d_out;

    int n    = in_sizes[0] / IN_CH;   // 50000
    int E    = in_sizes[1] / 2;       // 800000
    int Etot = E + n;                 // + self loops
    const int* src = ei;
    const int* dst = ei + E;

    float *h1, *o1, *h2, *as1, *ad1, *m1, *den1, *as2, *ad2, *m2, *den2;
    cudaGetSymbolAddress((void**)&h1,   g_h1);
    cudaGetSymbolAddress((void**)&o1,   g_o1);
    cudaGetSymbolAddress((void**)&h2,   g_h2);
    cudaGetSymbolAddress((void**)&as1,  g_as1);
    cudaGetSymbolAddress((void**)&ad1,  g_ad1);
    cudaGetSymbolAddress((void**)&m1,   g_m1);
    cudaGetSymbolAddress((void**)&den1, g_den1);
    cudaGetSymbolAddress((void**)&as2,  g_as2);
    cudaGetSymbolAddress((void**)&ad2,  g_ad2);
    cudaGetSymbolAddress((void**)&m2,   g_m2);
    cudaGetSymbolAddress((void**)&den2, g_den2);

    // init accumulators
    fill_k<<<(n*C1 + 255)/256, 256>>>(o1, 0.f, n*C1);
    fill_k<<<(n*HEADS + 255)/256, 256>>>(m1, -FLT_MAX, n*HEADS);
    fill_k<<<(n*HEADS + 255)/256, 256>>>(den1, 0.f, n*HEADS);
    fill_k<<<(n + 255)/256, 256>>>(m2, -FLT_MAX, n);
    fill_k<<<(n + 255)/256, 256>>>(den2, 0.f, n);
    fill_k<<<(n*OUT_CH + 255)/256, 256>>>(out, 0.f, n*OUT_CH);

    // ---- layer 1 ----
    {
        dim3 grid(C1/64, (n + 63)/64);
        gemm_tiled<<<grid, 256>>>(x, W1, h1, n, C1, IN_CH);
    }
    attn_coeff<<<(n*HEADS + 255)/256, 256>>>(h1, att_s1, att_d1, as1, ad1, n, HEADS, HID);
    edge_max_k<<<(Etot + 255)/256, 256>>>(src, dst, as1, ad1, m1, Etot, E, HEADS);
    edge_sum_k<<<(Etot + 255)/256, 256>>>(src, dst, as1, ad1, m1, den1, Etot, E, HEADS);
    aggregate_k<256, 32, 8><<<Etot, 256>>>(src, dst, as1, ad1, m1, den1, h1, o1, Etot, E);
    relu_bias_k<<<(n*C1 + 255)/256, 256>>>(o1, b1, n*C1, C1);

    // ---- layer 2 ----
    {
        dim3 grid(OUT_CH/64, (n + 63)/64);
        gemm_tiled<<<grid, 256>>>(o1, W2, h2, n, OUT_CH, C1);
    }
    attn_coeff<<<(n + 255)/256, 256>>>(h2, att_s2, att_d2, as2, ad2, n, 1, OUT_CH);
    edge_max_k<<<(Etot + 255)/256, 256>>>(src, dst, as2, ad2, m2, Etot, E, 1);
    edge_sum_k<<<(Etot + 255)/256, 256>>>(src, dst, as2, ad2, m2, den2, Etot, E, 1);
    aggregate_k<64, 64, 1><<<(Etot + 3)/4, 256>>>(src, dst, as2, ad2, m2, den2, h2, out, Etot, E);
    add_bias_k<<<(n*OUT_CH + 255)/256, 256>>>(out, b2, n*OUT_CH, OUT_CH);
}

// round 3
// speedup vs baseline: 2.6570x; 2.6570x over previous
#include <cuda_runtime.h>
#include <float.h>

// Problem constants (fixed-shape problem)
#define NNODES 50000
#define EMAX   800000
#define ETOTMAX (EMAX + NNODES)
#define IN_CH  256
#define HEADS  8
#define HID    32
#define C1     (HEADS*HID)   // 256
#define OUT_CH 64
#define NEG_SLOPE 0.2f
#define CAP 96               // smem-cached logits per node (fallback recompute beyond)

// ---------------- scratch (device globals) ---------------------------------
__device__ float g_h1 [NNODES*C1];      // x @ W1
__device__ float g_o1 [NNODES*C1];      // layer-1 output (bias+relu applied)
__device__ float g_h2 [NNODES*OUT_CH];  // o1 @ W2
__device__ float g_as1[NNODES*HEADS];
__device__ float g_ad1[NNODES*HEADS];
__device__ float g_as2[NNODES];
__device__ float g_ad2[NNODES];
__device__ int   g_deg[NNODES];
__device__ int   g_rowptr[NNODES+1];
__device__ int   g_cursor[NNODES];
__device__ int   g_csrc[ETOTMAX];

// ---------------- CSR build -------------------------------------------------
__global__ void fill_int_k(int* __restrict__ p, int v, int n) {
    int i = blockIdx.x*blockDim.x + threadIdx.x;
    if (i < n) p[i] = v;
}

__global__ void hist_k(const int* __restrict__ dst, int* __restrict__ deg, int E) {
    int i = blockIdx.x*blockDim.x + threadIdx.x;
    if (i < E) atomicAdd(&deg[dst[i]], 1);
}

// single-block inclusive scan -> exclusive rowptr
__global__ void scan_k(const int* __restrict__ deg, int* __restrict__ rowptr, int n) {
    __shared__ int sm[1024];
    __shared__ int carry;
    int tid = threadIdx.x;
    if (tid == 0) carry = 0;
    __syncthreads();
    for (int base = 0; base < n; base += 1024) {
        int v = (base + tid < n) ? deg[base + tid] : 0;
        sm[tid] = v;
        __syncthreads();
        for (int off = 1; off < 1024; off <<= 1) {
            int t = (tid >= off) ? sm[tid - off] : 0;
            __syncthreads();
            sm[tid] += t;
            __syncthreads();
        }
        if (base + tid < n) rowptr[base + tid + 1] = carry + sm[tid];
        __syncthreads();
        if (tid == 0) carry += sm[1023];
        __syncthreads();
    }
    if (tid == 0) rowptr[0] = 0;
}

__global__ void scatter_k(const int* __restrict__ src, const int* __restrict__ dst,
                          int* __restrict__ cursor, int* __restrict__ csrc,
                          int Etot, int E) {
    int i = blockIdx.x*blockDim.x + threadIdx.x;
    if (i >= Etot) return;
    int s, d;
    if (i < E) { s = src[i]; d = dst[i]; }
    else       { s = d = i - E; }
    int pos = atomicAdd(&cursor[d], 1);
    csrc[pos] = s;
}

// ---------------- SGEMM: C[M,N] = A[M,K] @ B[K,N], BM=128, BK=8 ------------
template<int BN, int TN>
__global__ void gemm_k(const float* __restrict__ A, const float* __restrict__ B,
                       float* __restrict__ C, int M, int N, int K) {
    const int BM = 128, BK = 8, TM = 8;
    const int TX = BN / TN;   // threads along N (16)
    __shared__ float As[BK][BM];
    __shared__ float Bs[BK][BN];
    int tid = threadIdx.x;
    int tx = tid % TX, ty = tid / TX;
    int row0 = blockIdx.y * BM, col0 = blockIdx.x * BN;

    float acc[TM][TN] = {};

    int ar = tid >> 1;           // 0..127
    int ak = (tid & 1) * 4;      // 0 or 4

    for (int k0 = 0; k0 < K; k0 += BK) {
        {
            int gr = row0 + ar;
            float4 v = make_float4(0.f,0.f,0.f,0.f);
            if (gr < M) v = *(const float4*)(A + (size_t)gr*K + k0 + ak);
            As[ak+0][ar]=v.x; As[ak+1][ar]=v.y; As[ak+2][ar]=v.z; As[ak+3][ar]=v.w;
        }
        if (BN == 128) {
            int bk = tid >> 5;           // 0..7
            int bn = (tid & 31) * 4;
            *(float4*)&Bs[bk][bn] = *(const float4*)(B + (size_t)(k0+bk)*N + col0 + bn);
        } else {                          // BN == 64
            int bk = tid >> 5;
            int bn = (tid & 31) * 2;
            *(float2*)&Bs[bk][bn] = *(const float2*)(B + (size_t)(k0+bk)*N + col0 + bn);
        }
        __syncthreads();

        #pragma unroll
        for (int kk = 0; kk < BK; kk++) {
            float av[TM], bv[TN];
            #pragma unroll
            for (int i=0;i<TM;i++) av[i] = As[kk][ty*TM+i];
            #pragma unroll
            for (int j=0;j<TN;j++) bv[j] = Bs[kk][tx*TN+j];
            #pragma unroll
            for (int i=0;i<TM;i++)
                #pragma unroll
                for (int j=0;j<TN;j++)
                    acc[i][j] = fmaf(av[i], bv[j], acc[i][j]);
        }
        __syncthreads();
    }

    #pragma unroll
    for (int i=0;i<TM;i++) {
        int gr = row0 + ty*TM + i;
        if (gr < M) {
            #pragma unroll
            for (int j=0;j<TN;j+=4) {
                float4 o = make_float4(acc[i][j],acc[i][j+1],acc[i][j+2],acc[i][j+3]);
                *(float4*)(C + (size_t)gr*N + col0 + tx*TN + j) = o;
            }
        }
    }
}

// ---------------- attention coefficients ------------------------------------
__global__ void attn_coeff(const float* __restrict__ h,
                           const float* __restrict__ att_s,
                           const float* __restrict__ att_d,
                           float* __restrict__ as, float* __restrict__ ad,
                           int n, int heads, int F) {
    int i = blockIdx.x * blockDim.x + threadIdx.x;
    if (i >= n * heads) return;
    int node = i / heads, hh = i - node * heads;
    const float* row = h + (size_t)node * heads * F + hh * F;
    const float* ws = att_s + hh * F;
    const float* wd = att_d + hh * F;
    float s = 0.f, d = 0.f;
    #pragma unroll 8
    for (int f = 0; f < F; f++) {
        float v = row[f];
        s = fmaf(v, ws[f], s);
        d = fmaf(v, wd[f], d);
    }
    as[i] = s;
    ad[i] = d;
}

// ---------------- fused per-node softmax + aggregation, layer 1 -------------
// One warp per dst node. 8 head-groups of 4 lanes for softmax.
// Aggregation: lane l covers channels [8l, 8l+8); head = l>>2 (matches group).
__global__ void node_l1(const int* __restrict__ rowptr, const int* __restrict__ csrc,
                        const float* __restrict__ as, const float* __restrict__ ad,
                        const float* __restrict__ h, const float* __restrict__ bias,
                        float* __restrict__ out, int n) {
    __shared__ float buf[8][8][CAP];   // [warp][head][slot]
    int w = threadIdx.x >> 5, lane = threadIdx.x & 31;
    int node = blockIdx.x * 8 + w;
    if (node >= n) return;
    int r0 = rowptr[node];
    int deg = rowptr[node+1] - r0;
    int g = lane >> 2, li = lane & 3;
    float ad_h = ad[node*8 + g];

    // phase 1: logits + max
    float mymax = -FLT_MAX;
    for (int k = li; k < deg; k += 4) {
        int s = csrc[r0 + k];
        float e = as[s*8 + g] + ad_h;
        e = e > 0.f ? e : NEG_SLOPE * e;
        if (k < CAP) buf[w][g][k] = e;
        mymax = fmaxf(mymax, e);
    }
    mymax = fmaxf(mymax, __shfl_xor_sync(0xffffffffu, mymax, 1));
    mymax = fmaxf(mymax, __shfl_xor_sync(0xffffffffu, mymax, 2));
    __syncwarp();

    // phase 2: exp + sum
    float sum = 0.f;
    for (int k = li; k < deg; k += 4) {
        float e;
        if (k < CAP) e = buf[w][g][k];
        else {
            int s = csrc[r0 + k];
            e = as[s*8 + g] + ad_h;
            e = e > 0.f ? e : NEG_SLOPE * e;
        }
        float x = __expf(e - mymax);
        if (k < CAP) buf[w][g][k] = x;
        sum += x;
    }
    sum += __shfl_xor_sync(0xffffffffu, sum, 1);
    sum += __shfl_xor_sync(0xffffffffu, sum, 2);
    float invden = 1.f / sum;
    __syncwarp();

    // phase 3: aggregation (coalesced gather of h[s])
    float4 acc0 = make_float4(0,0,0,0), acc1 = make_float4(0,0,0,0);
    for (int base = 0; base < deg; base += 32) {
        int myS = (base + lane < deg) ? csrc[r0 + base + lane] : 0;
        int kmax = min(32, deg - base);
        for (int kk = 0; kk < kmax; kk++) {
            int k = base + kk;
            int s = __shfl_sync(0xffffffffu, myS, kk);
            float alpha;
            if (k < CAP) alpha = buf[w][g][k] * invden;
            else {
                float e = as[s*8 + g] + ad_h;
                e = e > 0.f ? e : NEG_SLOPE * e;
                alpha = __expf(e - mymax) * invden;
            }
            const float4* hp = (const float4*)(h + (size_t)s*C1 + lane*8);
            float4 a = hp[0], b = hp[1];
            acc0.x = fmaf(alpha, a.x, acc0.x); acc0.y = fmaf(alpha, a.y, acc0.y);
            acc0.z = fmaf(alpha, a.z, acc0.z); acc0.w = fmaf(alpha, a.w, acc0.w);
            acc1.x = fmaf(alpha, b.x, acc1.x); acc1.y = fmaf(alpha, b.y, acc1.y);
            acc1.z = fmaf(alpha, b.z, acc1.z); acc1.w = fmaf(alpha, b.w, acc1.w);
        }
    }
    const float4* bp = (const float4*)(bias + lane*8);
    float4 b0 = bp[0], b1 = bp[1];
    acc0.x = fmaxf(acc0.x + b0.x, 0.f); acc0.y = fmaxf(acc0.y + b0.y, 0.f);
    acc0.z = fmaxf(acc0.z + b0.z, 0.f); acc0.w = fmaxf(acc0.w + b0.w, 0.f);
    acc1.x = fmaxf(acc1.x + b1.x, 0.f); acc1.y = fmaxf(acc1.y + b1.y, 0.f);
    acc1.z = fmaxf(acc1.z + b1.z, 0.f); acc1.w = fmaxf(acc1.w + b1.w, 0.f);
    float4* op = (float4*)(out + (size_t)node*C1 + lane*8);
    op[0] = acc0; op[1] = acc1;
}

// ---------------- fused per-node softmax + aggregation, layer 2 -------------
// One warp per dst node; single head; lane l covers channels [2l, 2l+2).
__global__ void node_l2(const int* __restrict__ rowptr, const int* __restrict__ csrc,
                        const float* __restrict__ as, const float* __restrict__ ad,
                        const float* __restrict__ h, const float* __restrict__ bias,
                        float* __restrict__ out, int n) {
    __shared__ float buf[8][CAP];
    int w = threadIdx.x >> 5, lane = threadIdx.x & 31;
    int node = blockIdx.x * 8 + w;
    if (node >= n) return;
    int r0 = rowptr[node];
    int deg = rowptr[node+1] - r0;
    float ad_h = ad[node];

    float mymax = -FLT_MAX;
    for (int k = lane; k < deg; k += 32) {
        int s = csrc[r0 + k];
        float e = as[s] + ad_h;
        e = e > 0.f ? e : NEG_SLOPE * e;
        if (k < CAP) buf[w][k] = e;
        mymax = fmaxf(mymax, e);
    }
    #pragma unroll
    for (int m = 1; m < 32; m <<= 1)
        mymax = fmaxf(mymax, __shfl_xor_sync(0xffffffffu, mymax, m));
    __syncwarp();

    float sum = 0.f;
    for (int k = lane; k < deg; k += 32) {
        float e;
        if (k < CAP) e = buf[w][k];
        else {
            int s = csrc[r0 + k];
            e = as[s] + ad_h;
            e = e > 0.f ? e : NEG_SLOPE * e;
        }
        float x = __expf(e - mymax);
        if (k < CAP) buf[w][k] = x;
        sum += x;
    }
    #pragma unroll
    for (int m = 1; m < 32; m <<= 1)
        sum += __shfl_xor_sync(0xffffffffu, sum, m);
    float invden = 1.f / sum;
    __syncwarp();

    float2 acc = make_float2(0.f, 0.f);
    for (int base = 0; base < deg; base += 32) {
        int myS = (base + lane < deg) ? csrc[r0 + base + lane] : 0;
        int kmax = min(32, deg - base);
        for (int kk = 0; kk < kmax; kk++) {
            int k = base + kk;
            int s = __shfl_sync(0xffffffffu, myS, kk);
            float alpha;
            if (k < CAP) alpha = buf[w][k] * invden;
            else {
                float e = as[s] + ad_h;
                e = e > 0.f ? e : NEG_SLOPE * e;
                alpha = __expf(e - mymax) * invden;
            }
            float2 v = *(const float2*)(h + (size_t)s*OUT_CH + lane*2);
            acc.x = fmaf(alpha, v.x, acc.x);
            acc.y = fmaf(alpha, v.y, acc.y);
        }
    }
    acc.x += bias[lane*2];
    acc.y += bias[lane*2+1];
    *(float2*)(out + (size_t)node*OUT_CH + lane*2) = acc;
}

// ---------------- launch ----------------------------------------------------
extern "C" void kernel_launch(void* const* d_in, const int* in_sizes, int n_in,
                              void* d_out, int out_size) {
    const float* x      = (const float*)d_in[0];
    const int*   ei     = (const int*)d_in[1];     // int32 edge_index
    const float* W1     = (const float*)d_in[2];
    const float* att_s1 = (const float*)d_in[3];
    const float* att_d1 = (const float*)d_in[4];
    const float* b1     = (const float*)d_in[5];
    const float* W2     = (const float*)d_in[6];
    const float* att_s2 = (const float*)d_in[7];
    const float* att_d2 = (const float*)d_in[8];
    const float* b2     = (const float*)d_in[9];
    float* out = (float*)d_out;

    int n    = in_sizes[0] / IN_CH;   // 50000
    int E    = in_sizes[1] / 2;       // 800000
    int Etot = E + n;
    const int* src = ei;
    const int* dst = ei + E;

    float *h1, *o1, *h2, *as1, *ad1, *as2, *ad2;
    int *deg, *rowptr, *cursor, *csrc;
    cudaGetSymbolAddress((void**)&h1,     g_h1);
    cudaGetSymbolAddress((void**)&o1,     g_o1);
    cudaGetSymbolAddress((void**)&h2,     g_h2);
    cudaGetSymbolAddress((void**)&as1,    g_as1);
    cudaGetSymbolAddress((void**)&ad1,    g_ad1);
    cudaGetSymbolAddress((void**)&as2,    g_as2);
    cudaGetSymbolAddress((void**)&ad2,    g_ad2);
    cudaGetSymbolAddress((void**)&deg,    g_deg);
    cudaGetSymbolAddress((void**)&rowptr, g_rowptr);
    cudaGetSymbolAddress((void**)&cursor, g_cursor);
    cudaGetSymbolAddress((void**)&csrc,   g_csrc);

    // ---- CSR build (shared by both layers) ----
    fill_int_k<<<(n + 255)/256, 256>>>(deg, 1, n);            // self-loop baked in
    hist_k<<<(E + 255)/256, 256>>>(dst, deg, E);
    scan_k<<<1, 1024>>>(deg, rowptr, n);
    cudaMemcpyAsync(cursor, rowptr, n*sizeof(int), cudaMemcpyDeviceToDevice);
    scatter_k<<<(Etot + 255)/256, 256>>>(src, dst, cursor, csrc, Etot, E);

    // ---- layer 1 ----
    {
        dim3 grid(C1/128, (n + 127)/128);
        gemm_k<128,8><<<grid, 256>>>(x, W1, h1, n, C1, IN_CH);
    }
    attn_coeff<<<(n*HEADS + 255)/256, 256>>>(h1, att_s1, att_d1, as1, ad1, n, HEADS, HID);
    node_l1<<<(n + 7)/8, 256>>>(rowptr, csrc, as1, ad1, h1, b1, o1, n);

    // ---- layer 2 ----
    {
        dim3 grid(OUT_CH/64, (n + 127)/128);
        gemm_k<64,4><<<grid, 256>>>(o1, W2, h2, n, OUT_CH, C1);
    }
    attn_coeff<<<(n + 255)/256, 256>>>(h2, att_s2, att_d2, as2, ad2, n, 1, OUT_CH);
    node_l2<<<(n + 7)/8, 256>>>(rowptr, csrc, as2, ad2, h2, b2, out, n);
}

// round 4
// speedup vs baseline: 3.2500x; 1.2232x over previous
#include <cuda_runtime.h>
#include <float.h>
#include <mma.h>

using namespace nvcuda;

// Problem constants (fixed-shape problem)
#define NNODES 50000
#define NPAD   50048            // NNODES rounded up to 128 (wmma tile)
#define EMAX   800000
#define ETOTMAX (EMAX + NNODES)
#define IN_CH  256
#define HEADS  8
#define HID    32
#define C1     (HEADS*HID)   // 256
#define OUT_CH 64
#define NEG_SLOPE 0.2f
#define CAP 96               // smem-cached logits per node

// ---------------- scratch (device globals) ---------------------------------
__device__ float g_h1 [NPAD*C1];        // x @ W1 (tf32), padded rows
__device__ float g_o1 [NNODES*C1];      // layer-1 output (bias+relu applied)
__device__ float g_h2 [NNODES*OUT_CH];  // o1 @ W2
__device__ float g_as1[NNODES*HEADS];
__device__ float g_ad1[NNODES*HEADS];
__device__ float g_as2[NNODES];
__device__ float g_ad2[NNODES];
__device__ int   g_deg[NNODES];
__device__ int   g_rowptr[NNODES+1];
__device__ int   g_cursor[NNODES];
__device__ int   g_csrc[ETOTMAX];
__device__ int   g_bsums[64];

// ---------------- CSR build -------------------------------------------------
__global__ void fill_int_k(int* __restrict__ p, int v, int n) {
    int i = blockIdx.x*blockDim.x + threadIdx.x;
    if (i < n) p[i] = v;
}

__global__ void hist_k(const int* __restrict__ dst, int* __restrict__ deg, int E) {
    int i = blockIdx.x*blockDim.x + threadIdx.x;
    if (i < E) atomicAdd(&deg[dst[i]], 1);
}

// per-block inclusive scan of 1024 elements
__global__ void bscan_k(const int* __restrict__ deg, int* __restrict__ rowptr,
                        int* __restrict__ bsums, int n) {
    __shared__ int sm[1024];
    int base = blockIdx.x * 1024, tid = threadIdx.x;
    int v = (base + tid < n) ? deg[base + tid] : 0;
    sm[tid] = v;
    __syncthreads();
    for (int off = 1; off < 1024; off <<= 1) {
        int t = (tid >= off) ? sm[tid - off] : 0;
        __syncthreads();
        sm[tid] += t;
        __syncthreads();
    }
    if (base + tid < n) rowptr[base + tid + 1] = sm[tid];
    if (tid == 1023) bsums[blockIdx.x] = sm[1023];
}

__global__ void pscan_k(int* __restrict__ bsums, int nb) {
    __shared__ int sm[64];
    int tid = threadIdx.x;
    sm[tid] = (tid < nb) ? bsums[tid] : 0;
    __syncthreads();
    for (int off = 1; off < 64; off <<= 1) {
        int t = (tid >= off) ? sm[tid - off] : 0;
        __syncthreads();
        sm[tid] += t;
        __syncthreads();
    }
    if (tid < nb) bsums[tid] = sm[tid];
}

__global__ void addoff_k(int* __restrict__ rowptr, const int* __restrict__ bsums, int n) {
    int i = blockIdx.x*blockDim.x + threadIdx.x;
    if (i == 0) rowptr[0] = 0;
    if (i < n) {
        int blk = i >> 10;
        if (blk > 0) rowptr[i + 1] += bsums[blk - 1];
    }
}

__global__ void scatter_k(const int* __restrict__ src, const int* __restrict__ dst,
                          int* __restrict__ cursor, int* __restrict__ csrc,
                          int Etot, int E) {
    int i = blockIdx.x*blockDim.x + threadIdx.x;
    if (i >= Etot) return;
    int s, d;
    if (i < E) { s = src[i]; d = dst[i]; }
    else       { s = d = i - E; }
    int pos = atomicAdd(&cursor[d], 1);
    csrc[pos] = s;
}

// ---------------- TF32 WMMA GEMM: C[M,N] = A[M,K] @ B[K,N] -----------------
// BM=128, BN=128, BK=32. 8 warps in 2x4; warp tile 64x32 (4x2 wmma 16x16x8).
// Requires N%128==0, K%32==0. A rows guarded (zero beyond M). C rows padded.
__global__ void gemm_tf32(const float* __restrict__ A, const float* __restrict__ B,
                          float* __restrict__ C, int M, int N, int K) {
    const int BM = 128, BN = 128, BK = 32;
    __shared__ float As[BM][BK + 4];
    __shared__ float Bs[BK][BN + 4];
    int tid = threadIdx.x;
    int wid = tid >> 5;
    int wr = wid >> 2, wc = wid & 3;          // warp row (0..1), col (0..3)
    int row0 = blockIdx.y * BM, col0 = blockIdx.x * BN;

    wmma::fragment<wmma::accumulator, 16, 16, 8, float> acc[4][2];
    #pragma unroll
    for (int i = 0; i < 4; i++)
        #pragma unroll
        for (int j = 0; j < 2; j++)
            wmma::fill_fragment(acc[i][j], 0.f);

    for (int k0 = 0; k0 < K; k0 += BK) {
        // load A tile: 128 rows x 32 cols = 1024 float4; 4 per thread
        #pragma unroll
        for (int i = 0; i < 4; i++) {
            int id = tid + i * 256;
            int r = id >> 3;              // 0..127
            int c4 = (id & 7) * 4;        // 0..28
            int gr = row0 + r;
            float4 v = make_float4(0.f,0.f,0.f,0.f);
            if (gr < M) v = *(const float4*)(A + (size_t)gr * K + k0 + c4);
            *(float4*)&As[r][c4] = v;
        }
        // load B tile: 32 rows x 128 cols = 1024 float4; 4 per thread
        #pragma unroll
        for (int i = 0; i < 4; i++) {
            int id = tid + i * 256;
            int r = id >> 5;              // 0..31
            int c4 = (id & 31) * 4;       // 0..124
            float4 v = *(const float4*)(B + (size_t)(k0 + r) * N + col0 + c4);
            *(float4*)&Bs[r][c4] = v;
        }
        __syncthreads();

        #pragma unroll
        for (int kk = 0; kk < BK / 8; kk++) {
            wmma::fragment<wmma::matrix_a, 16, 16, 8, wmma::precision::tf32, wmma::row_major> af[4];
            wmma::fragment<wmma::matrix_b, 16, 16, 8, wmma::precision::tf32, wmma::row_major> bf[2];
            #pragma unroll
            for (int i = 0; i < 4; i++) {
                wmma::load_matrix_sync(af[i], &As[wr*64 + i*16][kk*8], BK + 4);
                #pragma unroll
                for (int t = 0; t < af[i].num_elements; t++)
                    af[i].x[t] = wmma::__float_to_tf32(af[i].x[t]);
            }
            #pragma unroll
            for (int j = 0; j < 2; j++) {
                wmma::load_matrix_sync(bf[j], &Bs[kk*8][wc*32 + j*16], BN + 4);
                #pragma unroll
                for (int t = 0; t < bf[j].num_elements; t++)
                    bf[j].x[t] = wmma::__float_to_tf32(bf[j].x[t]);
            }
            #pragma unroll
            for (int i = 0; i < 4; i++)
                #pragma unroll
                for (int j = 0; j < 2; j++)
                    wmma::mma_sync(acc[i][j], af[i], bf[j], acc[i][j]);
        }
        __syncthreads();
    }

    // store (C padded; rows beyond M are scratch)
    #pragma unroll
    for (int i = 0; i < 4; i++)
        #pragma unroll
        for (int j = 0; j < 2; j++) {
            int gr = row0 + wr*64 + i*16;
            wmma::store_matrix_sync(C + (size_t)gr * N + col0 + wc*32 + j*16,
                                    acc[i][j], N, wmma::mem_row_major);
        }
}

// ---------------- SGEMM (fp32 SIMT) for layer 2 -----------------------------
template<int BN, int TN>
__global__ void gemm_k(const float* __restrict__ A, const float* __restrict__ B,
                       float* __restrict__ C, int M, int N, int K) {
    const int BM = 128, BK = 8, TM = 8;
    const int TX = BN / TN;
    __shared__ float As[BK][BM];
    __shared__ float Bs[BK][BN];
    int tid = threadIdx.x;
    int tx = tid % TX, ty = tid / TX;
    int row0 = blockIdx.y * BM, col0 = blockIdx.x * BN;

    float acc[TM][TN] = {};
    int ar = tid >> 1;
    int ak = (tid & 1) * 4;

    for (int k0 = 0; k0 < K; k0 += BK) {
        {
            int gr = row0 + ar;
            float4 v = make_float4(0.f,0.f,0.f,0.f);
            if (gr < M) v = *(const float4*)(A + (size_t)gr*K + k0 + ak);
            As[ak+0][ar]=v.x; As[ak+1][ar]=v.y; As[ak+2][ar]=v.z; As[ak+3][ar]=v.w;
        }
        {
            int bk = tid >> 5;
            int bn = (tid & 31) * 2;
            if (bn < BN)
                *(float2*)&Bs[bk][bn] = *(const float2*)(B + (size_t)(k0+bk)*N + col0 + bn);
        }
        __syncthreads();

        #pragma unroll
        for (int kk = 0; kk < BK; kk++) {
            float av[TM], bv[TN];
            #pragma unroll
            for (int i=0;i<TM;i++) av[i] = As[kk][ty*TM+i];
            #pragma unroll
            for (int j=0;j<TN;j++) bv[j] = Bs[kk][tx*TN+j];
            #pragma unroll
            for (int i=0;i<TM;i++)
                #pragma unroll
                for (int j=0;j<TN;j++)
                    acc[i][j] = fmaf(av[i], bv[j], acc[i][j]);
        }
        __syncthreads();
    }

    #pragma unroll
    for (int i=0;i<TM;i++) {
        int gr = row0 + ty*TM + i;
        if (gr < M) {
            #pragma unroll
            for (int j=0;j<TN;j+=4) {
                float4 o = make_float4(acc[i][j],acc[i][j+1],acc[i][j+2],acc[i][j+3]);
                *(float4*)(C + (size_t)gr*N + col0 + tx*TN + j) = o;
            }
        }
    }
}

// ---------------- attention coefficients ------------------------------------
__global__ void attn_coeff(const float* __restrict__ h,
                           const float* __restrict__ att_s,
                           const float* __restrict__ att_d,
                           float* __restrict__ as, float* __restrict__ ad,
                           int n, int heads, int F) {
    int i = blockIdx.x * blockDim.x + threadIdx.x;
    if (i >= n * heads) return;
    int node = i / heads, hh = i - node * heads;
    const float* row = h + (size_t)node * heads * F + hh * F;
    const float* ws = att_s + hh * F;
    const float* wd = att_d + hh * F;
    float s = 0.f, d = 0.f;
    #pragma unroll 8
    for (int f = 0; f < F; f++) {
        float v = row[f];
        s = fmaf(v, ws[f], s);
        d = fmaf(v, wd[f], d);
    }
    as[i] = s;
    ad[i] = d;
}

// ---------------- fused per-node softmax + aggregation, layer 1 -------------
__global__ void node_l1(const int* __restrict__ rowptr, const int* __restrict__ csrc,
                        const float* __restrict__ as, const float* __restrict__ ad,
                        const float* __restrict__ h, const float* __restrict__ bias,
                        float* __restrict__ out, int n) {
    __shared__ float buf[8][8][CAP];   // [warp][head][slot]
    int w = threadIdx.x >> 5, lane = threadIdx.x & 31;
    int node = blockIdx.x * 8 + w;
    if (node >= n) return;
    int r0 = rowptr[node];
    int deg = rowptr[node+1] - r0;
    int g = lane >> 2, li = lane & 3;
    float ad_h = ad[node*8 + g];

    float mymax = -FLT_MAX;
    for (int k = li; k < deg; k += 4) {
        int s = csrc[r0 + k];
        float e = as[s*8 + g] + ad_h;
        e = e > 0.f ? e : NEG_SLOPE * e;
        if (k < CAP) buf[w][g][k] = e;
        mymax = fmaxf(mymax, e);
    }
    mymax = fmaxf(mymax, __shfl_xor_sync(0xffffffffu, mymax, 1));
    mymax = fmaxf(mymax, __shfl_xor_sync(0xffffffffu, mymax, 2));
    __syncwarp();

    float sum = 0.f;
    for (int k = li; k < deg; k += 4) {
        float e;
        if (k < CAP) e = buf[w][g][k];
        else {
            int s = csrc[r0 + k];
            e = as[s*8 + g] + ad_h;
            e = e > 0.f ? e : NEG_SLOPE * e;
        }
        float x = __expf(e - mymax);
        if (k < CAP) buf[w][g][k] = x;
        sum += x;
    }
    sum += __shfl_xor_sync(0xffffffffu, sum, 1);
    sum += __shfl_xor_sync(0xffffffffu, sum, 2);
    float invden = 1.f / sum;
    __syncwarp();

    float4 acc0 = make_float4(0,0,0,0), acc1 = make_float4(0,0,0,0);
    for (int base = 0; base < deg; base += 32) {
        int myS = (base + lane < deg) ? csrc[r0 + base + lane] : 0;
        int kmax = min(32, deg - base);
        for (int kk = 0; kk < kmax; kk++) {
            int k = base + kk;
            int s = __shfl_sync(0xffffffffu, myS, kk);
            float alpha;
            if (k < CAP) alpha = buf[w][g][k] * invden;
            else {
                float e = as[s*8 + g] + ad_h;
                e = e > 0.f ? e : NEG_SLOPE * e;
                alpha = __expf(e - mymax) * invden;
            }
            const float4* hp = (const float4*)(h + (size_t)s*C1 + lane*8);
            float4 a = hp[0], b = hp[1];
            acc0.x = fmaf(alpha, a.x, acc0.x); acc0.y = fmaf(alpha, a.y, acc0.y);
            acc0.z = fmaf(alpha, a.z, acc0.z); acc0.w = fmaf(alpha, a.w, acc0.w);
            acc1.x = fmaf(alpha, b.x, acc1.x); acc1.y = fmaf(alpha, b.y, acc1.y);
            acc1.z = fmaf(alpha, b.z, acc1.z); acc1.w = fmaf(alpha, b.w, acc1.w);
        }
    }
    const float4* bp = (const float4*)(bias + lane*8);
    float4 b0 = bp[0], b1 = bp[1];
    acc0.x = fmaxf(acc0.x + b0.x, 0.f); acc0.y = fmaxf(acc0.y + b0.y, 0.f);
    acc0.z = fmaxf(acc0.z + b0.z, 0.f); acc0.w = fmaxf(acc0.w + b0.w, 0.f);
    acc1.x = fmaxf(acc1.x + b1.x, 0.f); acc1.y = fmaxf(acc1.y + b1.y, 0.f);
    acc1.z = fmaxf(acc1.z + b1.z, 0.f); acc1.w = fmaxf(acc1.w + b1.w, 0.f);
    float4* op = (float4*)(out + (size_t)node*C1 + lane*8);
    op[0] = acc0; op[1] = acc1;
}

// ---------------- fused per-node softmax + aggregation, layer 2 -------------
__global__ void node_l2(const int* __restrict__ rowptr, const int* __restrict__ csrc,
                        const float* __restrict__ as, const float* __restrict__ ad,
                        const float* __restrict__ h, const float* __restrict__ bias,
                        float* __restrict__ out, int n) {
    __shared__ float buf[8][CAP];
    int w = threadIdx.x >> 5, lane = threadIdx.x & 31;
    int node = blockIdx.x * 8 + w;
    if (node >= n) return;
    int r0 = rowptr[node];
    int deg = rowptr[node+1] - r0;
    float ad_h = ad[node];

    float mymax = -FLT_MAX;
    for (int k = lane; k < deg; k += 32) {
        int s = csrc[r0 + k];
        float e = as[s] + ad_h;
        e = e > 0.f ? e : NEG_SLOPE * e;
        if (k < CAP) buf[w][k] = e;
        mymax = fmaxf(mymax, e);
    }
    #pragma unroll
    for (int m = 1; m < 32; m <<= 1)
        mymax = fmaxf(mymax, __shfl_xor_sync(0xffffffffu, mymax, m));
    __syncwarp();

    float sum = 0.f;
    for (int k = lane; k < deg; k += 32) {
        float e;
        if (k < CAP) e = buf[w][k];
        else {
            int s = csrc[r0 + k];
            e = as[s] + ad_h;
            e = e > 0.f ? e : NEG_SLOPE * e;
        }
        float x = __expf(e - mymax);
        if (k < CAP) buf[w][k] = x;
        sum += x;
    }
    #pragma unroll
    for (int m = 1; m < 32; m <<= 1)
        sum += __shfl_xor_sync(0xffffffffu, sum, m);
    float invden = 1.f / sum;
    __syncwarp();

    float2 acc = make_float2(0.f, 0.f);
    for (int base = 0; base < deg; base += 32) {
        int myS = (base + lane < deg) ? csrc[r0 + base + lane] : 0;
        int kmax = min(32, deg - base);
        for (int kk = 0; kk < kmax; kk++) {
            int k = base + kk;
            int s = __shfl_sync(0xffffffffu, myS, kk);
            float alpha;
            if (k < CAP) alpha = buf[w][k] * invden;
            else {
                float e = as[s] + ad_h;
                e = e > 0.f ? e : NEG_SLOPE * e;
                alpha = __expf(e - mymax) * invden;
            }
            float2 v = *(const float2*)(h + (size_t)s*OUT_CH + lane*2);
            acc.x = fmaf(alpha, v.x, acc.x);
            acc.y = fmaf(alpha, v.y, acc.y);
        }
    }
    acc.x += bias[lane*2];
    acc.y += bias[lane*2+1];
    *(float2*)(out + (size_t)node*OUT_CH + lane*2) = acc;
}

// ---------------- launch ----------------------------------------------------
extern "C" void kernel_launch(void* const* d_in, const int* in_sizes, int n_in,
                              void* d_out, int out_size) {
    const float* x      = (const float*)d_in[0];
    const int*   ei     = (const int*)d_in[1];
    const float* W1     = (const float*)d_in[2];
    const float* att_s1 = (const float*)d_in[3];
    const float* att_d1 = (const float*)d_in[4];
    const float* b1     = (const float*)d_in[5];
    const float* W2     = (const float*)d_in[6];
    const float* att_s2 = (const float*)d_in[7];
    const float* att_d2 = (const float*)d_in[8];
    const float* b2     = (const float*)d_in[9];
    float* out = (float*)d_out;

    int n    = in_sizes[0] / IN_CH;   // 50000
    int E    = in_sizes[1] / 2;       // 800000
    int Etot = E + n;
    const int* src = ei;
    const int* dst = ei + E;

    float *h1, *o1, *h2, *as1, *ad1, *as2, *ad2;
    int *deg, *rowptr, *cursor, *csrc, *bsums;
    cudaGetSymbolAddress((void**)&h1,     g_h1);
    cudaGetSymbolAddress((void**)&o1,     g_o1);
    cudaGetSymbolAddress((void**)&h2,     g_h2);
    cudaGetSymbolAddress((void**)&as1,    g_as1);
    cudaGetSymbolAddress((void**)&ad1,    g_ad1);
    cudaGetSymbolAddress((void**)&as2,    g_as2);
    cudaGetSymbolAddress((void**)&ad2,    g_ad2);
    cudaGetSymbolAddress((void**)&deg,    g_deg);
    cudaGetSymbolAddress((void**)&rowptr, g_rowptr);
    cudaGetSymbolAddress((void**)&cursor, g_cursor);
    cudaGetSymbolAddress((void**)&csrc,   g_csrc);
    cudaGetSymbolAddress((void**)&bsums,  g_bsums);

    int nb = (n + 1023) / 1024;       // 49

    // ---- CSR build ----
    fill_int_k<<<(n + 255)/256, 256>>>(deg, 1, n);            // self-loop baked in
    hist_k<<<(E + 255)/256, 256>>>(dst, deg, E);
    bscan_k<<<nb, 1024>>>(deg, rowptr, bsums, n);
    pscan_k<<<1, 64>>>(bsums, nb);
    addoff_k<<<(n + 255)/256, 256>>>(rowptr, bsums, n);
    cudaMemcpyAsync(cursor, rowptr, n*sizeof(int), cudaMemcpyDeviceToDevice);
    scatter_k<<<(Etot + 255)/256, 256>>>(src, dst, cursor, csrc, Etot, E);

    // ---- layer 1 ----
    {
        dim3 grid(C1/128, (n + 127)/128);
        gemm_tf32<<<grid, 256>>>(x, W1, h1, n, C1, IN_CH);
    }
    attn_coeff<<<(n*HEADS + 255)/256, 256>>>(h1, att_s1, att_d1, as1, ad1, n, HEADS, HID);
    node_l1<<<(n + 7)/8, 256>>>(rowptr, csrc, as1, ad1, h1, b1, o1, n);

    // ---- layer 2 ----
    {
        dim3 grid(OUT_CH/64, (n + 127)/128);
        gemm_k<64,4><<<grid, 256>>>(o1, W2, h2, n, OUT_CH, C1);
    }
    attn_coeff<<<(n + 255)/256, 256>>>(h2, att_s2, att_d2, as2, ad2, n, 1, OUT_CH);
    node_l2<<<(n + 7)/8, 256>>>(rowptr, csrc, as2, ad2, h2, b2, out, n);
}

// round 5
// speedup vs baseline: 3.4113x; 1.0496x over previous
#include <cuda_runtime.h>
#include <cuda_bf16.h>
#include <float.h>
#include <mma.h>

using namespace nvcuda;

#define NNODES 50000
#define NPAD   50048
#define EMAX   800000
#define ETOTMAX (EMAX + NNODES)
#define IN_CH  256
#define HEADS  8
#define HID    32
#define C1     (HEADS*HID)   // 256
#define OUT_CH 64
#define NEG_SLOPE 0.2f
#define CAP 96

// ---------------- scratch ----------------------------------------------------
__device__ float          g_h1 [NPAD*C1];      // x @ W1 (fp32)
__device__ __nv_bfloat16  g_h1b[NPAD*C1];      // bf16 copy for gather
__device__ float          g_o1 [NNODES*C1];    // layer-1 output
__device__ float          g_h2 [NPAD*OUT_CH];  // o1 @ W2 (padded rows)
__device__ float g_as1[NNODES*HEADS];
__device__ float g_ad1[NNODES*HEADS];
__device__ float g_as2[NNODES];
__device__ float g_ad2[NNODES];
__device__ int   g_deg[NNODES];
__device__ int   g_rowptr[NNODES+1];
__device__ int   g_cursor[NNODES];
__device__ int   g_csrc[ETOTMAX];
__device__ int   g_bsums[64];

// ---------------- CSR build --------------------------------------------------
__global__ void fill_int_k(int* __restrict__ p, int v, int n) {
    int i = blockIdx.x*blockDim.x + threadIdx.x;
    if (i < n) p[i] = v;
}

__global__ void hist_k(const int* __restrict__ dst, int* __restrict__ deg, int E) {
    int i = blockIdx.x*blockDim.x + threadIdx.x;
    if (i < E) atomicAdd(&deg[dst[i]], 1);
}

__global__ void bscan_k(const int* __restrict__ deg, int* __restrict__ rowptr,
                        int* __restrict__ bsums, int n) {
    __shared__ int sm[1024];
    int base = blockIdx.x * 1024, tid = threadIdx.x;
    int v = (base + tid < n) ? deg[base + tid] : 0;
    sm[tid] = v;
    __syncthreads();
    for (int off = 1; off < 1024; off <<= 1) {
        int t = (tid >= off) ? sm[tid - off] : 0;
        __syncthreads();
        sm[tid] += t;
        __syncthreads();
    }
    if (base + tid < n) rowptr[base + tid + 1] = sm[tid];
    if (tid == 1023) bsums[blockIdx.x] = sm[1023];
}

__global__ void pscan_k(int* __restrict__ bsums, int nb) {
    __shared__ int sm[64];
    int tid = threadIdx.x;
    sm[tid] = (tid < nb) ? bsums[tid] : 0;
    __syncthreads();
    for (int off = 1; off < 64; off <<= 1) {
        int t = (tid >= off) ? sm[tid - off] : 0;
        __syncthreads();
        sm[tid] += t;
        __syncthreads();
    }
    if (tid < nb) bsums[tid] = sm[tid];
}

// finalize rowptr and also write cursor = rowptr start (no extra memcpy)
__global__ void addoff_k(int* __restrict__ rowptr, int* __restrict__ cursor,
                         const int* __restrict__ bsums, int n) {
    int i = blockIdx.x*blockDim.x + threadIdx.x;
    if (i >= n) return;
    int blk = i >> 10;
    int v = rowptr[i + 1] + (blk > 0 ? bsums[blk - 1] : 0);
    rowptr[i + 1] = v;
    if (i + 1 < n) cursor[i + 1] = v;
    if (i == 0) { rowptr[0] = 0; cursor[0] = 0; }
}

__global__ void scatter_k(const int* __restrict__ src, const int* __restrict__ dst,
                          int* __restrict__ cursor, int* __restrict__ csrc,
                          int Etot, int E) {
    int i = blockIdx.x*blockDim.x + threadIdx.x;
    if (i >= Etot) return;
    int s, d;
    if (i < E) { s = src[i]; d = dst[i]; }
    else       { s = d = i - E; }
    int pos = atomicAdd(&cursor[d], 1);
    csrc[pos] = s;
}

// ---------------- TF32 WMMA GEMM: C[M,N] = A[M,K] @ B[K,N] ------------------
// BM=128, BK=32, 8 warps arranged 2x4. BN=128: warp 64x32 (acc[4][2]);
// BN=64: warp 64x16 (acc[4][1]). C rows padded to multiple of 128.
template<int BN>
__global__ void gemm_tf32(const float* __restrict__ A, const float* __restrict__ B,
                          float* __restrict__ C, int M, int N, int K) {
    const int BM = 128, BK = 32;
    const int WN = BN / 4;           // warp tile in N (32 or 16)
    const int FN = WN / 16;          // frags in N (2 or 1)
    __shared__ float As[BM][BK + 4];
    __shared__ float Bs[BK][BN + 4];
    int tid = threadIdx.x;
    int wid = tid >> 5;
    int wr = wid >> 2, wc = wid & 3;
    int row0 = blockIdx.y * BM, col0 = blockIdx.x * BN;

    wmma::fragment<wmma::accumulator, 16, 16, 8, float> acc[4][FN];
    #pragma unroll
    for (int i = 0; i < 4; i++)
        #pragma unroll
        for (int j = 0; j < FN; j++)
            wmma::fill_fragment(acc[i][j], 0.f);

    for (int k0 = 0; k0 < K; k0 += BK) {
        #pragma unroll
        for (int i = 0; i < 4; i++) {               // A: 128x32 = 1024 float4
            int id = tid + i * 256;
            int r = id >> 3;
            int c4 = (id & 7) * 4;
            int gr = row0 + r;
            float4 v = make_float4(0.f,0.f,0.f,0.f);
            if (gr < M) v = *(const float4*)(A + (size_t)gr * K + k0 + c4);
            *(float4*)&As[r][c4] = v;
        }
        #pragma unroll
        for (int i = 0; i < BN/32; i++) {           // B: 32xBN
            int id = tid + i * 256;
            int r = id / (BN/4);
            int c4 = (id % (BN/4)) * 4;
            float4 v = *(const float4*)(B + (size_t)(k0 + r) * N + col0 + c4);
            *(float4*)&Bs[r][c4] = v;
        }
        __syncthreads();

        #pragma unroll
        for (int kk = 0; kk < BK / 8; kk++) {
            wmma::fragment<wmma::matrix_a, 16, 16, 8, wmma::precision::tf32, wmma::row_major> af[4];
            wmma::fragment<wmma::matrix_b, 16, 16, 8, wmma::precision::tf32, wmma::row_major> bf[FN];
            #pragma unroll
            for (int i = 0; i < 4; i++) {
                wmma::load_matrix_sync(af[i], &As[wr*64 + i*16][kk*8], BK + 4);
                #pragma unroll
                for (int t = 0; t < af[i].num_elements; t++)
                    af[i].x[t] = wmma::__float_to_tf32(af[i].x[t]);
            }
            #pragma unroll
            for (int j = 0; j < FN; j++) {
                wmma::load_matrix_sync(bf[j], &Bs[kk*8][wc*WN + j*16], BN + 4);
                #pragma unroll
                for (int t = 0; t < bf[j].num_elements; t++)
                    bf[j].x[t] = wmma::__float_to_tf32(bf[j].x[t]);
            }
            #pragma unroll
            for (int i = 0; i < 4; i++)
                #pragma unroll
                for (int j = 0; j < FN; j++)
                    wmma::mma_sync(acc[i][j], af[i], bf[j], acc[i][j]);
        }
        __syncthreads();
    }

    #pragma unroll
    for (int i = 0; i < 4; i++)
        #pragma unroll
        for (int j = 0; j < FN; j++) {
            int gr = row0 + wr*64 + i*16;
            wmma::store_matrix_sync(C + (size_t)gr * N + col0 + wc*WN + j*16,
                                    acc[i][j], N, wmma::mem_row_major);
        }
}

// ---------------- attention coeff, layer 1 (+ bf16 convert) ----------------
__global__ void attn1_fused(const float* __restrict__ h,
                            const float* __restrict__ att_s,
                            const float* __restrict__ att_d,
                            float* __restrict__ as, float* __restrict__ ad,
                            __nv_bfloat16* __restrict__ hb, int n) {
    int i = blockIdx.x * blockDim.x + threadIdx.x;
    if (i >= n * HEADS) return;
    int node = i / HEADS, hh = i - node * HEADS;
    const float* row = h + (size_t)node * C1 + hh * HID;
    __nv_bfloat16* brow = hb + (size_t)node * C1 + hh * HID;
    const float* ws = att_s + hh * HID;
    const float* wd = att_d + hh * HID;
    float s = 0.f, d = 0.f;
    #pragma unroll
    for (int f = 0; f < HID; f += 2) {
        float v0 = row[f], v1 = row[f+1];
        s = fmaf(v0, ws[f], s); d = fmaf(v0, wd[f], d);
        s = fmaf(v1, ws[f+1], s); d = fmaf(v1, wd[f+1], d);
        *(__nv_bfloat162*)(brow + f) = __floats2bfloat162_rn(v0, v1);
    }
    as[i] = s;
    ad[i] = d;
}

__global__ void attn_coeff2(const float* __restrict__ h,
                            const float* __restrict__ att_s,
                            const float* __restrict__ att_d,
                            float* __restrict__ as, float* __restrict__ ad, int n) {
    int i = blockIdx.x * blockDim.x + threadIdx.x;
    if (i >= n) return;
    const float* row = h + (size_t)i * OUT_CH;
    float s = 0.f, d = 0.f;
    #pragma unroll 8
    for (int f = 0; f < OUT_CH; f++) {
        float v = row[f];
        s = fmaf(v, att_s[f], s);
        d = fmaf(v, att_d[f], d);
    }
    as[i] = s;
    ad[i] = d;
}

// ---------------- fused per-node softmax + aggregation, layer 1 -------------
__global__ void node_l1(const int* __restrict__ rowptr, const int* __restrict__ csrc,
                        const float* __restrict__ as, const float* __restrict__ ad,
                        const __nv_bfloat16* __restrict__ hb,
                        const float* __restrict__ bias,
                        float* __restrict__ out, int n) {
    __shared__ float buf[8][8][CAP];
    int w = threadIdx.x >> 5, lane = threadIdx.x & 31;
    int node = blockIdx.x * 8 + w;
    if (node >= n) return;
    int r0 = rowptr[node];
    int deg = rowptr[node+1] - r0;
    int g = lane >> 2, li = lane & 3;
    float ad_h = ad[node*8 + g];

    float mymax = -FLT_MAX;
    for (int k = li; k < deg; k += 4) {
        int s = csrc[r0 + k];
        float e = as[s*8 + g] + ad_h;
        e = e > 0.f ? e : NEG_SLOPE * e;
        if (k < CAP) buf[w][g][k] = e;
        mymax = fmaxf(mymax, e);
    }
    mymax = fmaxf(mymax, __shfl_xor_sync(0xffffffffu, mymax, 1));
    mymax = fmaxf(mymax, __shfl_xor_sync(0xffffffffu, mymax, 2));
    __syncwarp();

    float sum = 0.f;
    for (int k = li; k < deg; k += 4) {
        float e;
        if (k < CAP) e = buf[w][g][k];
        else {
            int s = csrc[r0 + k];
            e = as[s*8 + g] + ad_h;
            e = e > 0.f ? e : NEG_SLOPE * e;
        }
        float x = __expf(e - mymax);
        if (k < CAP) buf[w][g][k] = x;
        sum += x;
    }
    sum += __shfl_xor_sync(0xffffffffu, sum, 1);
    sum += __shfl_xor_sync(0xffffffffu, sum, 2);
    float invden = 1.f / sum;
    __syncwarp();

    float acc[8] = {};
    for (int base = 0; base < deg; base += 32) {
        int myS = (base + lane < deg) ? csrc[r0 + base + lane] : 0;
        int kmax = min(32, deg - base);
        int kk = 0;
        for (; kk + 1 < kmax; kk += 2) {
            int k0i = base + kk, k1i = base + kk + 1;
            int s0 = __shfl_sync(0xffffffffu, myS, kk);
            int s1 = __shfl_sync(0xffffffffu, myS, kk + 1);
            uint4 r0v = *(const uint4*)(hb + (size_t)s0*C1 + lane*8);
            uint4 r1v = *(const uint4*)(hb + (size_t)s1*C1 + lane*8);
            float a0, a1;
            if (k0i < CAP) a0 = buf[w][g][k0i] * invden;
            else {
                float e = as[s0*8 + g] + ad_h;
                e = e > 0.f ? e : NEG_SLOPE * e;
                a0 = __expf(e - mymax) * invden;
            }
            if (k1i < CAP) a1 = buf[w][g][k1i] * invden;
            else {
                float e = as[s1*8 + g] + ad_h;
                e = e > 0.f ? e : NEG_SLOPE * e;
                a1 = __expf(e - mymax) * invden;
            }
            const unsigned* u0 = &r0v.x;
            const unsigned* u1 = &r1v.x;
            #pragma unroll
            for (int q = 0; q < 4; q++) {
                float2 f0 = __bfloat1622float2(*(const __nv_bfloat162*)&u0[q]);
                float2 f1 = __bfloat1622float2(*(const __nv_bfloat162*)&u1[q]);
                acc[q*2+0] = fmaf(a0, f0.x, acc[q*2+0]);
                acc[q*2+1] = fmaf(a0, f0.y, acc[q*2+1]);
                acc[q*2+0] = fmaf(a1, f1.x, acc[q*2+0]);
                acc[q*2+1] = fmaf(a1, f1.y, acc[q*2+1]);
            }
        }
        if (kk < kmax) {
            int ki = base + kk;
            int s = __shfl_sync(0xffffffffu, myS, kk);
            uint4 rv = *(const uint4*)(hb + (size_t)s*C1 + lane*8);
            float a;
            if (ki < CAP) a = buf[w][g][ki] * invden;
            else {
                float e = as[s*8 + g] + ad_h;
                e = e > 0.f ? e : NEG_SLOPE * e;
                a = __expf(e - mymax) * invden;
            }
            const unsigned* u = &rv.x;
            #pragma unroll
            for (int q = 0; q < 4; q++) {
                float2 f = __bfloat1622float2(*(const __nv_bfloat162*)&u[q]);
                acc[q*2+0] = fmaf(a, f.x, acc[q*2+0]);
                acc[q*2+1] = fmaf(a, f.y, acc[q*2+1]);
            }
        }
    }
    float4 o0, o1;
    const float4* bp = (const float4*)(bias + lane*8);
    float4 b0 = bp[0], b1 = bp[1];
    o0.x = fmaxf(acc[0] + b0.x, 0.f); o0.y = fmaxf(acc[1] + b0.y, 0.f);
    o0.z = fmaxf(acc[2] + b0.z, 0.f); o0.w = fmaxf(acc[3] + b0.w, 0.f);
    o1.x = fmaxf(acc[4] + b1.x, 0.f); o1.y = fmaxf(acc[5] + b1.y, 0.f);
    o1.z = fmaxf(acc[6] + b1.z, 0.f); o1.w = fmaxf(acc[7] + b1.w, 0.f);
    float4* op = (float4*)(out + (size_t)node*C1 + lane*8);
    op[0] = o0; op[1] = o1;
}

// ---------------- fused per-node softmax + aggregation, layer 2 -------------
__global__ void node_l2(const int* __restrict__ rowptr, const int* __restrict__ csrc,
                        const float* __restrict__ as, const float* __restrict__ ad,
                        const float* __restrict__ h, const float* __restrict__ bias,
                        float* __restrict__ out, int n) {
    __shared__ float buf[8][CAP];
    int w = threadIdx.x >> 5, lane = threadIdx.x & 31;
    int node = blockIdx.x * 8 + w;
    if (node >= n) return;
    int r0 = rowptr[node];
    int deg = rowptr[node+1] - r0;
    float ad_h = ad[node];

    float mymax = -FLT_MAX;
    for (int k = lane; k < deg; k += 32) {
        int s = csrc[r0 + k];
        float e = as[s] + ad_h;
        e = e > 0.f ? e : NEG_SLOPE * e;
        if (k < CAP) buf[w][k] = e;
        mymax = fmaxf(mymax, e);
    }
    #pragma unroll
    for (int m = 1; m < 32; m <<= 1)
        mymax = fmaxf(mymax, __shfl_xor_sync(0xffffffffu, mymax, m));
    __syncwarp();

    float sum = 0.f;
    for (int k = lane; k < deg; k += 32) {
        float e;
        if (k < CAP) e = buf[w][k];
        else {
            int s = csrc[r0 + k];
            e = as[s] + ad_h;
            e = e > 0.f ? e : NEG_SLOPE * e;
        }
        float x = __expf(e - mymax);
        if (k < CAP) buf[w][k] = x;
        sum += x;
    }
    #pragma unroll
    for (int m = 1; m < 32; m <<= 1)
        sum += __shfl_xor_sync(0xffffffffu, sum, m);
    float invden = 1.f / sum;
    __syncwarp();

    float2 acc = make_float2(0.f, 0.f);
    for (int base = 0; base < deg; base += 32) {
        int myS = (base + lane < deg) ? csrc[r0 + base + lane] : 0;
        int kmax = min(32, deg - base);
        int kk = 0;
        for (; kk + 1 < kmax; kk += 2) {
            int k0i = base + kk, k1i = base + kk + 1;
            int s0 = __shfl_sync(0xffffffffu, myS, kk);
            int s1 = __shfl_sync(0xffffffffu, myS, kk + 1);
            float2 v0 = *(const float2*)(h + (size_t)s0*OUT_CH + lane*2);
            float2 v1 = *(const float2*)(h + (size_t)s1*OUT_CH + lane*2);
            float a0, a1;
            if (k0i < CAP) a0 = buf[w][k0i] * invden;
            else {
                float e = as[s0] + ad_h;
                e = e > 0.f ? e : NEG_SLOPE * e;
                a0 = __expf(e - mymax) * invden;
            }
            if (k1i < CAP) a1 = buf[w][k1i] * invden;
            else {
                float e = as[s1] + ad_h;
                e = e > 0.f ? e : NEG_SLOPE * e;
                a1 = __expf(e - mymax) * invden;
            }
            acc.x = fmaf(a0, v0.x, acc.x); acc.y = fmaf(a0, v0.y, acc.y);
            acc.x = fmaf(a1, v1.x, acc.x); acc.y = fmaf(a1, v1.y, acc.y);
        }
        if (kk < kmax) {
            int ki = base + kk;
            int s = __shfl_sync(0xffffffffu, myS, kk);
            float2 v = *(const float2*)(h + (size_t)s*OUT_CH + lane*2);
            float a;
            if (ki < CAP) a = buf[w][ki] * invden;
            else {
                float e = as[s] + ad_h;
                e = e > 0.f ? e : NEG_SLOPE * e;
                a = __expf(e - mymax) * invden;
            }
            acc.x = fmaf(a, v.x, acc.x); acc.y = fmaf(a, v.y, acc.y);
        }
    }
    acc.x += bias[lane*2];
    acc.y += bias[lane*2+1];
    *(float2*)(out + (size_t)node*OUT_CH + lane*2) = acc;
}

// ---------------- launch ----------------------------------------------------
extern "C" void kernel_launch(void* const* d_in, const int* in_sizes, int n_in,
                              void* d_out, int out_size) {
    const float* x      = (const float*)d_in[0];
    const int*   ei     = (const int*)d_in[1];
    const float* W1     = (const float*)d_in[2];
    const float* att_s1 = (const float*)d_in[3];
    const float* att_d1 = (const float*)d_in[4];
    const float* b1     = (const float*)d_in[5];
    const float* W2     = (const float*)d_in[6];
    const float* att_s2 = (const float*)d_in[7];
    const float* att_d2 = (const float*)d_in[8];
    const float* b2     = (const float*)d_in[9];
    float* out = (float*)d_out;

    int n    = in_sizes[0] / IN_CH;   // 50000
    int E    = in_sizes[1] / 2;       // 800000
    int Etot = E + n;
    const int* src = ei;
    const int* dst = ei + E;

    float *h1, *o1, *h2, *as1, *ad1, *as2, *ad2;
    __nv_bfloat16* h1b;
    int *deg, *rowptr, *cursor, *csrc, *bsums;
    cudaGetSymbolAddress((void**)&h1,     g_h1);
    cudaGetSymbolAddress((void**)&h1b,    g_h1b);
    cudaGetSymbolAddress((void**)&o1,     g_o1);
    cudaGetSymbolAddress((void**)&h2,     g_h2);
    cudaGetSymbolAddress((void**)&as1,    g_as1);
    cudaGetSymbolAddress((void**)&ad1,    g_ad1);
    cudaGetSymbolAddress((void**)&as2,    g_as2);
    cudaGetSymbolAddress((void**)&ad2,    g_ad2);
    cudaGetSymbolAddress((void**)&deg,    g_deg);
    cudaGetSymbolAddress((void**)&rowptr, g_rowptr);
    cudaGetSymbolAddress((void**)&cursor, g_cursor);
    cudaGetSymbolAddress((void**)&csrc,   g_csrc);
    cudaGetSymbolAddress((void**)&bsums,  g_bsums);

    int nb = (n + 1023) / 1024;

    // ---- CSR build ----
    fill_int_k<<<(n + 255)/256, 256>>>(deg, 1, n);   // self-loop baked in
    hist_k<<<(E + 255)/256, 256>>>(dst, deg, E);
    bscan_k<<<nb, 1024>>>(deg, rowptr, bsums, n);
    pscan_k<<<1, 64>>>(bsums, nb);
    addoff_k<<<(n + 255)/256, 256>>>(rowptr, cursor, bsums, n);
    scatter_k<<<(Etot + 255)/256, 256>>>(src, dst, cursor, csrc, Etot, E);

    // ---- layer 1 ----
    {
        dim3 grid(C1/128, (n + 127)/128);
        gemm_tf32<128><<<grid, 256>>>(x, W1, h1, n, C1, IN_CH);
    }
    attn1_fused<<<(n*HEADS + 255)/256, 256>>>(h1, att_s1, att_d1, as1, ad1, h1b, n);
    node_l1<<<(n + 7)/8, 256>>>(rowptr, csrc, as1, ad1, h1b, b1, o1, n);

    // ---- layer 2 ----
    {
        dim3 grid(OUT_CH/64, (n + 127)/128);
        gemm_tf32<64><<<grid, 256>>>(o1, W2, h2, n, OUT_CH, C1);
    }
    attn_coeff2<<<(n + 255)/256, 256>>>(h2, att_s2, att_d2, as2, ad2, n);
    node_l2<<<(n + 7)/8, 256>>>(rowptr, csrc, as2, ad2, h2, b2, out, n);
}

// round 6
// speedup vs baseline: 3.4137x; 1.0007x over previous
#include <cuda_runtime.h>
#include <cuda_bf16.h>
#include <float.h>
#include <mma.h>

using namespace nvcuda;

#define NNODES 50000
#define NPAD   50048
#define EMAX   800000
#define ETOTMAX (EMAX + NNODES)
#define IN_CH  256
#define HEADS  8
#define HID    32
#define C1     (HEADS*HID)   // 256
#define OUT_CH 64
#define NEG_SLOPE 0.2f
#define CAP 96

// ---------------- scratch ----------------------------------------------------
__device__ float          g_h1 [NPAD*C1];      // x @ W1 (fp32)
__device__ __nv_bfloat16  g_h1b[NPAD*C1];      // bf16 copy for gather
__device__ float          g_o1 [NNODES*C1];    // layer-1 output
__device__ float          g_h2 [NPAD*OUT_CH];  // o1 @ W2 (padded rows)
__device__ float g_as1[NNODES*HEADS];
__device__ float g_ad1[NNODES*HEADS];
__device__ float g_as2[NNODES];
__device__ float g_ad2[NNODES];
__device__ int   g_deg[NNODES];
__device__ int   g_rowptr[NNODES+1];
__device__ int   g_cursor[NNODES];
__device__ int   g_csrc[ETOTMAX];
__device__ int   g_bsums[64];

// ---------------- CSR build --------------------------------------------------
__global__ void fill_int_k(int* __restrict__ p, int v, int n) {
    int i = blockIdx.x*blockDim.x + threadIdx.x;
    if (i < n) p[i] = v;
}

__global__ void hist_k(const int* __restrict__ dst, int* __restrict__ deg, int E) {
    int i = blockIdx.x*blockDim.x + threadIdx.x;
    if (i < E) atomicAdd(&deg[dst[i]], 1);
}

__global__ void bscan_k(const int* __restrict__ deg, int* __restrict__ rowptr,
                        int* __restrict__ bsums, int n) {
    __shared__ int sm[1024];
    int base = blockIdx.x * 1024, tid = threadIdx.x;
    int v = (base + tid < n) ? deg[base + tid] : 0;
    sm[tid] = v;
    __syncthreads();
    for (int off = 1; off < 1024; off <<= 1) {
        int t = (tid >= off) ? sm[tid - off] : 0;
        __syncthreads();
        sm[tid] += t;
        __syncthreads();
    }
    if (base + tid < n) rowptr[base + tid + 1] = sm[tid];
    if (tid == 1023) bsums[blockIdx.x] = sm[1023];
}

__global__ void pscan_k(int* __restrict__ bsums, int nb) {
    __shared__ int sm[64];
    int tid = threadIdx.x;
    sm[tid] = (tid < nb) ? bsums[tid] : 0;
    __syncthreads();
    for (int off = 1; off < 64; off <<= 1) {
        int t = (tid >= off) ? sm[tid - off] : 0;
        __syncthreads();
        sm[tid] += t;
        __syncthreads();
    }
    if (tid < nb) bsums[tid] = sm[tid];
}

// finalize rowptr and also write cursor = rowptr start (no extra memcpy)
__global__ void addoff_k(int* __restrict__ rowptr, int* __restrict__ cursor,
                         const int* __restrict__ bsums, int n) {
    int i = blockIdx.x*blockDim.x + threadIdx.x;
    if (i >= n) return;
    int blk = i >> 10;
    int v = rowptr[i + 1] + (blk > 0 ? bsums[blk - 1] : 0);
    rowptr[i + 1] = v;
    if (i + 1 < n) cursor[i + 1] = v;
    if (i == 0) { rowptr[0] = 0; cursor[0] = 0; }
}

__global__ void scatter_k(const int* __restrict__ src, const int* __restrict__ dst,
                          int* __restrict__ cursor, int* __restrict__ csrc,
                          int Etot, int E) {
    int i = blockIdx.x*blockDim.x + threadIdx.x;
    if (i >= Etot) return;
    int s, d;
    if (i < E) { s = src[i]; d = dst[i]; }
    else       { s = d = i - E; }
    int pos = atomicAdd(&cursor[d], 1);
    csrc[pos] = s;
}

// ---------------- TF32 WMMA GEMM: C[M,N] = A[M,K] @ B[K,N] ------------------
// BM=128, BK=32, 8 warps arranged 2x4. BN=128: warp 64x32 (acc[4][2]);
// BN=64: warp 64x16 (acc[4][1]). C rows padded to multiple of 128.
template<int BN>
__global__ void gemm_tf32(const float* __restrict__ A, const float* __restrict__ B,
                          float* __restrict__ C, int M, int N, int K) {
    const int BM = 128, BK = 32;
    const int WN = BN / 4;           // warp tile in N (32 or 16)
    const int FN = WN / 16;          // frags in N (2 or 1)
    __shared__ float As[BM][BK + 4];
    __shared__ float Bs[BK][BN + 4];
    int tid = threadIdx.x;
    int wid = tid >> 5;
    int wr = wid >> 2, wc = wid & 3;
    int row0 = blockIdx.y * BM, col0 = blockIdx.x * BN;

    wmma::fragment<wmma::accumulator, 16, 16, 8, float> acc[4][FN];
    #pragma unroll
    for (int i = 0; i < 4; i++)
        #pragma unroll
        for (int j = 0; j < FN; j++)
            wmma::fill_fragment(acc[i][j], 0.f);

    for (int k0 = 0; k0 < K; k0 += BK) {
        #pragma unroll
        for (int i = 0; i < 4; i++) {               // A: 128x32 = 1024 float4
            int id = tid + i * 256;
            int r = id >> 3;
            int c4 = (id & 7) * 4;
            int gr = row0 + r;
            float4 v = make_float4(0.f,0.f,0.f,0.f);
            if (gr < M) v = *(const float4*)(A + (size_t)gr * K + k0 + c4);
            *(float4*)&As[r][c4] = v;
        }
        #pragma unroll
        for (int i = 0; i < BN/32; i++) {           // B: 32xBN
            int id = tid + i * 256;
            int r = id / (BN/4);
            int c4 = (id % (BN/4)) * 4;
            float4 v = *(const float4*)(B + (size_t)(k0 + r) * N + col0 + c4);
            *(float4*)&Bs[r][c4] = v;
        }
        __syncthreads();

        #pragma unroll
        for (int kk = 0; kk < BK / 8; kk++) {
            wmma::fragment<wmma::matrix_a, 16, 16, 8, wmma::precision::tf32, wmma::row_major> af[4];
            wmma::fragment<wmma::matrix_b, 16, 16, 8, wmma::precision::tf32, wmma::row_major> bf[FN];
            #pragma unroll
            for (int i = 0; i < 4; i++) {
                wmma::load_matrix_sync(af[i], &As[wr*64 + i*16][kk*8], BK + 4);
                #pragma unroll
                for (int t = 0; t < af[i].num_elements; t++)
                    af[i].x[t] = wmma::__float_to_tf32(af[i].x[t]);
            }
            #pragma unroll
            for (int j = 0; j < FN; j++) {
                wmma::load_matrix_sync(bf[j], &Bs[kk*8][wc*WN + j*16], BN + 4);
                #pragma unroll
                for (int t = 0; t < bf[j].num_elements; t++)
                    bf[j].x[t] = wmma::__float_to_tf32(bf[j].x[t]);
            }
            #pragma unroll
            for (int i = 0; i < 4; i++)
                #pragma unroll
                for (int j = 0; j < FN; j++)
                    wmma::mma_sync(acc[i][j], af[i], bf[j], acc[i][j]);
        }
        __syncthreads();
    }

    #pragma unroll
    for (int i = 0; i < 4; i++)
        #pragma unroll
        for (int j = 0; j < FN; j++) {
            int gr = row0 + wr*64 + i*16;
            wmma::store_matrix_sync(C + (size_t)gr * N + col0 + wc*WN + j*16,
                                    acc[i][j], N, wmma::mem_row_major);
        }
}

// ---------------- attention coeff, layer 1 (+ bf16 convert) ----------------
__global__ void attn1_fused(const float* __restrict__ h,
                            const float* __restrict__ att_s,
                            const float* __restrict__ att_d,
                            float* __restrict__ as, float* __restrict__ ad,
                            __nv_bfloat16* __restrict__ hb, int n) {
    int i = blockIdx.x * blockDim.x + threadIdx.x;
    if (i >= n * HEADS) return;
    int node = i / HEADS, hh = i - node * HEADS;
    const float* row = h + (size_t)node * C1 + hh * HID;
    __nv_bfloat16* brow = hb + (size_t)node * C1 + hh * HID;
    const float* ws = att_s + hh * HID;
    const float* wd = att_d + hh * HID;
    float s = 0.f, d = 0.f;
    #pragma unroll
    for (int f = 0; f < HID; f += 2) {
        float v0 = row[f], v1 = row[f+1];
        s = fmaf(v0, ws[f], s); d = fmaf(v0, wd[f], d);
        s = fmaf(v1, ws[f+1], s); d = fmaf(v1, wd[f+1], d);
        *(__nv_bfloat162*)(brow + f) = __floats2bfloat162_rn(v0, v1);
    }
    as[i] = s;
    ad[i] = d;
}

__global__ void attn_coeff2(const float* __restrict__ h,
                            const float* __restrict__ att_s,
                            const float* __restrict__ att_d,
                            float* __restrict__ as, float* __restrict__ ad, int n) {
    int i = blockIdx.x * blockDim.x + threadIdx.x;
    if (i >= n) return;
    const float* row = h + (size_t)i * OUT_CH;
    float s = 0.f, d = 0.f;
    #pragma unroll 8
    for (int f = 0; f < OUT_CH; f++) {
        float v = row[f];
        s = fmaf(v, att_s[f], s);
        d = fmaf(v, att_d[f], d);
    }
    as[i] = s;
    ad[i] = d;
}

// ---------------- fused per-node softmax + aggregation, layer 1 -------------
__global__ void node_l1(const int* __restrict__ rowptr, const int* __restrict__ csrc,
                        const float* __restrict__ as, const float* __restrict__ ad,
                        const __nv_bfloat16* __restrict__ hb,
                        const float* __restrict__ bias,
                        float* __restrict__ out, int n) {
    __shared__ float buf[8][8][CAP];
    int w = threadIdx.x >> 5, lane = threadIdx.x & 31;
    int node = blockIdx.x * 8 + w;
    if (node >= n) return;
    int r0 = rowptr[node];
    int deg = rowptr[node+1] - r0;
    int g = lane >> 2, li = lane & 3;
    float ad_h = ad[node*8 + g];

    float mymax = -FLT_MAX;
    for (int k = li; k < deg; k += 4) {
        int s = csrc[r0 + k];
        float e = as[s*8 + g] + ad_h;
        e = e > 0.f ? e : NEG_SLOPE * e;
        if (k < CAP) buf[w][g][k] = e;
        mymax = fmaxf(mymax, e);
    }
    mymax = fmaxf(mymax, __shfl_xor_sync(0xffffffffu, mymax, 1));
    mymax = fmaxf(mymax, __shfl_xor_sync(0xffffffffu, mymax, 2));
    __syncwarp();

    float sum = 0.f;
    for (int k = li; k < deg; k += 4) {
        float e;
        if (k < CAP) e = buf[w][g][k];
        else {
            int s = csrc[r0 + k];
            e = as[s*8 + g] + ad_h;
            e = e > 0.f ? e : NEG_SLOPE * e;
        }
        float x = __expf(e - mymax);
        if (k < CAP) buf[w][g][k] = x;
        sum += x;
    }
    sum += __shfl_xor_sync(0xffffffffu, sum, 1);
    sum += __shfl_xor_sync(0xffffffffu, sum, 2);
    float invden = 1.f / sum;
    __syncwarp();

    float acc[8] = {};
    for (int base = 0; base < deg; base += 32) {
        int myS = (base + lane < deg) ? csrc[r0 + base + lane] : 0;
        int kmax = min(32, deg - base);
        int kk = 0;
        for (; kk + 1 < kmax; kk += 2) {
            int k0i = base + kk, k1i = base + kk + 1;
            int s0 = __shfl_sync(0xffffffffu, myS, kk);
            int s1 = __shfl_sync(0xffffffffu, myS, kk + 1);
            uint4 r0v = *(const uint4*)(hb + (size_t)s0*C1 + lane*8);
            uint4 r1v = *(const uint4*)(hb + (size_t)s1*C1 + lane*8);
            float a0, a1;
            if (k0i < CAP) a0 = buf[w][g][k0i] * invden;
            else {
                float e = as[s0*8 + g] + ad_h;
                e = e > 0.f ? e : NEG_SLOPE * e;
                a0 = __expf(e - mymax) * invden;
            }
            if (k1i < CAP) a1 = buf[w][g][k1i] * invden;
            else {
                float e = as[s1*8 + g] + ad_h;
                e = e > 0.f ? e : NEG_SLOPE * e;
                a1 = __expf(e - mymax) * invden;
            }
            const unsigned* u0 = &r0v.x;
            const unsigned* u1 = &r1v.x;
            #pragma unroll
            for (int q = 0; q < 4; q++) {
                float2 f0 = __bfloat1622float2(*(const __nv_bfloat162*)&u0[q]);
                float2 f1 = __bfloat1622float2(*(const __nv_bfloat162*)&u1[q]);
                acc[q*2+0] = fmaf(a0, f0.x, acc[q*2+0]);
                acc[q*2+1] = fmaf(a0, f0.y, acc[q*2+1]);
                acc[q*2+0] = fmaf(a1, f1.x, acc[q*2+0]);
                acc[q*2+1] = fmaf(a1, f1.y, acc[q*2+1]);
            }
        }
        if (kk < kmax) {
            int ki = base + kk;
            int s = __shfl_sync(0xffffffffu, myS, kk);
            uint4 rv = *(const uint4*)(hb + (size_t)s*C1 + lane*8);
            float a;
            if (ki < CAP) a = buf[w][g][ki] * invden;
            else {
                float e = as[s*8 + g] + ad_h;
                e = e > 0.f ? e : NEG_SLOPE * e;
                a = __expf(e - mymax) * invden;
            }
            const unsigned* u = &rv.x;
            #pragma unroll
            for (int q = 0; q < 4; q++) {
                float2 f = __bfloat1622float2(*(const __nv_bfloat162*)&u[q]);
                acc[q*2+0] = fmaf(a, f.x, acc[q*2+0]);
                acc[q*2+1] = fmaf(a, f.y, acc[q*2+1]);
            }
        }
    }
    float4 o0, o1;
    const float4* bp = (const float4*)(bias + lane*8);
    float4 b0 = bp[0], b1 = bp[1];
    o0.x = fmaxf(acc[0] + b0.x, 0.f); o0.y = fmaxf(acc[1] + b0.y, 0.f);
    o0.z = fmaxf(acc[2] + b0.z, 0.f); o0.w = fmaxf(acc[3] + b0.w, 0.f);
    o1.x = fmaxf(acc[4] + b1.x, 0.f); o1.y = fmaxf(acc[5] + b1.y, 0.f);
    o1.z = fmaxf(acc[6] + b1.z, 0.f); o1.w = fmaxf(acc[7] + b1.w, 0.f);
    float4* op = (float4*)(out + (size_t)node*C1 + lane*8);
    op[0] = o0; op[1] = o1;
}

// ---------------- fused per-node softmax + aggregation, layer 2 -------------
__global__ void node_l2(const int* __restrict__ rowptr, const int* __restrict__ csrc,
                        const float* __restrict__ as, const float* __restrict__ ad,
                        const float* __restrict__ h, const float* __restrict__ bias,
                        float* __restrict__ out, int n) {
    __shared__ float buf[8][CAP];
    int w = threadIdx.x >> 5, lane = threadIdx.x & 31;
    int node = blockIdx.x * 8 + w;
    if (node >= n) return;
    int r0 = rowptr[node];
    int deg = rowptr[node+1] - r0;
    float ad_h = ad[node];

    float mymax = -FLT_MAX;
    for (int k = lane; k < deg; k += 32) {
        int s = csrc[r0 + k];
        float e = as[s] + ad_h;
        e = e > 0.f ? e : NEG_SLOPE * e;
        if (k < CAP) buf[w][k] = e;
        mymax = fmaxf(mymax, e);
    }
    #pragma unroll
    for (int m = 1; m < 32; m <<= 1)
        mymax = fmaxf(mymax, __shfl_xor_sync(0xffffffffu, mymax, m));
    __syncwarp();

    float sum = 0.f;
    for (int k = lane; k < deg; k += 32) {
        float e;
        if (k < CAP) e = buf[w][k];
        else {
            int s = csrc[r0 + k];
            e = as[s] + ad_h;
            e = e > 0.f ? e : NEG_SLOPE * e;
        }
        float x = __expf(e - mymax);
        if (k < CAP) buf[w][k] = x;
        sum += x;
    }
    #pragma unroll
    for (int m = 1; m < 32; m <<= 1)
        sum += __shfl_xor_sync(0xffffffffu, sum, m);
    float invden = 1.f / sum;
    __syncwarp();

    float2 acc = make_float2(0.f, 0.f);
    for (int base = 0; base < deg; base += 32) {
        int myS = (base + lane < deg) ? csrc[r0 + base + lane] : 0;
        int kmax = min(32, deg - base);
        int kk = 0;
        for (; kk + 1 < kmax; kk += 2) {
            int k0i = base + kk, k1i = base + kk + 1;
            int s0 = __shfl_sync(0xffffffffu, myS, kk);
            int s1 = __shfl_sync(0xffffffffu, myS, kk + 1);
            float2 v0 = *(const float2*)(h + (size_t)s0*OUT_CH + lane*2);
            float2 v1 = *(const float2*)(h + (size_t)s1*OUT_CH + lane*2);
            float a0, a1;
            if (k0i < CAP) a0 = buf[w][k0i] * invden;
            else {
                float e = as[s0] + ad_h;
                e = e > 0.f ? e : NEG_SLOPE * e;
                a0 = __expf(e - mymax) * invden;
            }
            if (k1i < CAP) a1 = buf[w][k1i] * invden;
            else {
                float e = as[s1] + ad_h;
                e = e > 0.f ? e : NEG_SLOPE * e;
                a1 = __expf(e - mymax) * invden;
            }
            acc.x = fmaf(a0, v0.x, acc.x); acc.y = fmaf(a0, v0.y, acc.y);
            acc.x = fmaf(a1, v1.x, acc.x); acc.y = fmaf(a1, v1.y, acc.y);
        }
        if (kk < kmax) {
            int ki = base + kk;
            int s = __shfl_sync(0xffffffffu, myS, kk);
            float2 v = *(const float2*)(h + (size_t)s*OUT_CH + lane*2);
            float a;
            if (ki < CAP) a = buf[w][ki] * invden;
            else {
                float e = as[s] + ad_h;
                e = e > 0.f ? e : NEG_SLOPE * e;
                a = __expf(e - mymax) * invden;
            }
            acc.x = fmaf(a, v.x, acc.x); acc.y = fmaf(a, v.y, acc.y);
        }
    }
    acc.x += bias[lane*2];
    acc.y += bias[lane*2+1];
    *(float2*)(out + (size_t)node*OUT_CH + lane*2) = acc;
}

// ---------------- launch ----------------------------------------------------
extern "C" void kernel_launch(void* const* d_in, const int* in_sizes, int n_in,
                              void* d_out, int out_size) {
    const float* x      = (const float*)d_in[0];
    const int*   ei     = (const int*)d_in[1];
    const float* W1     = (const float*)d_in[2];
    const float* att_s1 = (const float*)d_in[3];
    const float* att_d1 = (const float*)d_in[4];
    const float* b1     = (const float*)d_in[5];
    const float* W2     = (const float*)d_in[6];
    const float* att_s2 = (const float*)d_in[7];
    const float* att_d2 = (const float*)d_in[8];
    const float* b2     = (const float*)d_in[9];
    float* out = (float*)d_out;

    int n    = in_sizes[0] / IN_CH;   // 50000
    int E    = in_sizes[1] / 2;       // 800000
    int Etot = E + n;
    const int* src = ei;
    const int* dst = ei + E;

    float *h1, *o1, *h2, *as1, *ad1, *as2, *ad2;
    __nv_bfloat16* h1b;
    int *deg, *rowptr, *cursor, *csrc, *bsums;
    cudaGetSymbolAddress((void**)&h1,     g_h1);
    cudaGetSymbolAddress((void**)&h1b,    g_h1b);
    cudaGetSymbolAddress((void**)&o1,     g_o1);
    cudaGetSymbolAddress((void**)&h2,     g_h2);
    cudaGetSymbolAddress((void**)&as1,    g_as1);
    cudaGetSymbolAddress((void**)&ad1,    g_ad1);
    cudaGetSymbolAddress((void**)&as2,    g_as2);
    cudaGetSymbolAddress((void**)&ad2,    g_ad2);
    cudaGetSymbolAddress((void**)&deg,    g_deg);
    cudaGetSymbolAddress((void**)&rowptr, g_rowptr);
    cudaGetSymbolAddress((void**)&cursor, g_cursor);
    cudaGetSymbolAddress((void**)&csrc,   g_csrc);
    cudaGetSymbolAddress((void**)&bsums,  g_bsums);

    int nb = (n + 1023) / 1024;

    // ---- CSR build ----
    fill_int_k<<<(n + 255)/256, 256>>>(deg, 1, n);   // self-loop baked in
    hist_k<<<(E + 255)/256, 256>>>(dst, deg, E);
    bscan_k<<<nb, 1024>>>(deg, rowptr, bsums, n);
    pscan_k<<<1, 64>>>(bsums, nb);
    addoff_k<<<(n + 255)/256, 256>>>(rowptr, cursor, bsums, n);
    scatter_k<<<(Etot + 255)/256, 256>>>(src, dst, cursor, csrc, Etot, E);

    // ---- layer 1 ----
    {
        dim3 grid(C1/128, (n + 127)/128);
        gemm_tf32<128><<<grid, 256>>>(x, W1, h1, n, C1, IN_CH);
    }
    attn1_fused<<<(n*HEADS + 255)/256, 256>>>(h1, att_s1, att_d1, as1, ad1, h1b, n);
    node_l1<<<(n + 7)/8, 256>>>(rowptr, csrc, as1, ad1, h1b, b1, o1, n);

    // ---- layer 2 ----
    {
        dim3 grid(OUT_CH/64, (n + 127)/128);
        gemm_tf32<64><<<grid, 256>>>(o1, W2, h2, n, OUT_CH, C1);
    }
    attn_coeff2<<<(n + 255)/256, 256>>>(h2, att_s2, att_d2, as2, ad2, n);
    node_l2<<<(n + 7)/8, 256>>>(rowptr, csrc, as2, ad2, h2, b2, out, n);
}

// round 7
// speedup vs baseline: 3.4570x; 1.0127x over previous
#include <cuda_runtime.h>
#include <cuda_bf16.h>
#include <float.h>
#include <mma.h>

using namespace nvcuda;

#define NNODES 50000
#define NPAD   50048
#define EMAX   800000
#define ETOTMAX (EMAX + NNODES)
#define IN_CH  256
#define HEADS  8
#define HID    32
#define C1     (HEADS*HID)   // 256
#define OUT_CH 64
#define NEG_SLOPE 0.2f
#define CAP 96

// ---------------- scratch ----------------------------------------------------
__device__ float          g_h1 [NPAD*C1];      // x @ W1 (fp32)
__device__ __nv_bfloat16  g_h1b[NPAD*C1];      // bf16 copy for gather
__device__ float          g_o1 [NNODES*C1];    // layer-1 output
__device__ float          g_h2 [NPAD*OUT_CH];  // o1 @ W2 (padded rows)
__device__ float g_as1[NNODES*HEADS];
__device__ float g_ad1[NNODES*HEADS];
__device__ float g_as2[NNODES];
__device__ float g_ad2[NNODES];
__device__ int   g_deg[NNODES];
__device__ int   g_rowptr[NNODES+1];
__device__ int   g_cursor[NNODES];
__device__ int   g_csrc[ETOTMAX];
__device__ int   g_bsums[64];

// ---------------- CSR build --------------------------------------------------
__global__ void fill_int_k(int* __restrict__ p, int v, int n) {
    int i = blockIdx.x*blockDim.x + threadIdx.x;
    if (i < n) p[i] = v;
}

__global__ void hist_k(const int* __restrict__ dst, int* __restrict__ deg, int E) {
    int i = blockIdx.x*blockDim.x + threadIdx.x;
    if (i < E) atomicAdd(&deg[dst[i]], 1);
}

__global__ void bscan_k(const int* __restrict__ deg, int* __restrict__ rowptr,
                        int* __restrict__ bsums, int n) {
    __shared__ int sm[1024];
    int base = blockIdx.x * 1024, tid = threadIdx.x;
    int v = (base + tid < n) ? deg[base + tid] : 0;
    sm[tid] = v;
    __syncthreads();
    for (int off = 1; off < 1024; off <<= 1) {
        int t = (tid >= off) ? sm[tid - off] : 0;
        __syncthreads();
        sm[tid] += t;
        __syncthreads();
    }
    if (base + tid < n) rowptr[base + tid + 1] = sm[tid];
    if (tid == 1023) bsums[blockIdx.x] = sm[1023];
}

__global__ void pscan_k(int* __restrict__ bsums, int nb) {
    __shared__ int sm[64];
    int tid = threadIdx.x;
    sm[tid] = (tid < nb) ? bsums[tid] : 0;
    __syncthreads();
    for (int off = 1; off < 64; off <<= 1) {
        int t = (tid >= off) ? sm[tid - off] : 0;
        __syncthreads();
        sm[tid] += t;
        __syncthreads();
    }
    if (tid < nb) bsums[tid] = sm[tid];
}

// finalize rowptr and also write cursor = rowptr start (no extra memcpy)
__global__ void addoff_k(int* __restrict__ rowptr, int* __restrict__ cursor,
                         const int* __restrict__ bsums, int n) {
    int i = blockIdx.x*blockDim.x + threadIdx.x;
    if (i >= n) return;
    int blk = i >> 10;
    int v = rowptr[i + 1] + (blk > 0 ? bsums[blk - 1] : 0);
    rowptr[i + 1] = v;
    if (i + 1 < n) cursor[i + 1] = v;
    if (i == 0) { rowptr[0] = 0; cursor[0] = 0; }
}

__global__ void scatter_k(const int* __restrict__ src, const int* __restrict__ dst,
                          int* __restrict__ cursor, int* __restrict__ csrc,
                          int Etot, int E) {
    int i = blockIdx.x*blockDim.x + threadIdx.x;
    if (i >= Etot) return;
    int s, d;
    if (i < E) { s = src[i]; d = dst[i]; }
    else       { s = d = i - E; }
    int pos = atomicAdd(&cursor[d], 1);
    csrc[pos] = s;
}

// ---------------- TF32 WMMA GEMM: C[M,N] = A[M,K] @ B[K,N] ------------------
// BM=128, BK=32, 8 warps arranged 2x4. BN=128: warp 64x32 (acc[4][2]);
// BN=64: warp 64x16 (acc[4][1]). C rows padded to multiple of 128.
template<int BN>
__global__ void gemm_tf32(const float* __restrict__ A, const float* __restrict__ B,
                          float* __restrict__ C, int M, int N, int K) {
    const int BM = 128, BK = 32;
    const int WN = BN / 4;           // warp tile in N (32 or 16)
    const int FN = WN / 16;          // frags in N (2 or 1)
    __shared__ float As[BM][BK + 4];
    __shared__ float Bs[BK][BN + 4];
    int tid = threadIdx.x;
    int wid = tid >> 5;
    int wr = wid >> 2, wc = wid & 3;
    int row0 = blockIdx.y * BM, col0 = blockIdx.x * BN;

    wmma::fragment<wmma::accumulator, 16, 16, 8, float> acc[4][FN];
    #pragma unroll
    for (int i = 0; i < 4; i++)
        #pragma unroll
        for (int j = 0; j < FN; j++)
            wmma::fill_fragment(acc[i][j], 0.f);

    for (int k0 = 0; k0 < K; k0 += BK) {
        #pragma unroll
        for (int i = 0; i < 4; i++) {               // A: 128x32 = 1024 float4
            int id = tid + i * 256;
            int r = id >> 3;
            int c4 = (id & 7) * 4;
            int gr = row0 + r;
            float4 v = make_float4(0.f,0.f,0.f,0.f);
            if (gr < M) v = *(const float4*)(A + (size_t)gr * K + k0 + c4);
            *(float4*)&As[r][c4] = v;
        }
        #pragma unroll
        for (int i = 0; i < BN/32; i++) {           // B: 32xBN
            int id = tid + i * 256;
            int r = id / (BN/4);
            int c4 = (id % (BN/4)) * 4;
            float4 v = *(const float4*)(B + (size_t)(k0 + r) * N + col0 + c4);
            *(float4*)&Bs[r][c4] = v;
        }
        __syncthreads();

        #pragma unroll
        for (int kk = 0; kk < BK / 8; kk++) {
            wmma::fragment<wmma::matrix_a, 16, 16, 8, wmma::precision::tf32, wmma::row_major> af[4];
            wmma::fragment<wmma::matrix_b, 16, 16, 8, wmma::precision::tf32, wmma::row_major> bf[FN];
            #pragma unroll
            for (int i = 0; i < 4; i++) {
                wmma::load_matrix_sync(af[i], &As[wr*64 + i*16][kk*8], BK + 4);
                #pragma unroll
                for (int t = 0; t < af[i].num_elements; t++)
                    af[i].x[t] = wmma::__float_to_tf32(af[i].x[t]);
            }
            #pragma unroll
            for (int j = 0; j < FN; j++) {
                wmma::load_matrix_sync(bf[j], &Bs[kk*8][wc*WN + j*16], BN + 4);
                #pragma unroll
                for (int t = 0; t < bf[j].num_elements; t++)
                    bf[j].x[t] = wmma::__float_to_tf32(bf[j].x[t]);
            }
            #pragma unroll
            for (int i = 0; i < 4; i++)
                #pragma unroll
                for (int j = 0; j < FN; j++)
                    wmma::mma_sync(acc[i][j], af[i], bf[j], acc[i][j]);
        }
        __syncthreads();
    }

    #pragma unroll
    for (int i = 0; i < 4; i++)
        #pragma unroll
        for (int j = 0; j < FN; j++) {
            int gr = row0 + wr*64 + i*16;
            wmma::store_matrix_sync(C + (size_t)gr * N + col0 + wc*WN + j*16,
                                    acc[i][j], N, wmma::mem_row_major);
        }
}

// ---------------- attention coeff, layer 1 (+ bf16 convert) ----------------
__global__ void attn1_fused(const float* __restrict__ h,
                            const float* __restrict__ att_s,
                            const float* __restrict__ att_d,
                            float* __restrict__ as, float* __restrict__ ad,
                            __nv_bfloat16* __restrict__ hb, int n) {
    int i = blockIdx.x * blockDim.x + threadIdx.x;
    if (i >= n * HEADS) return;
    int node = i / HEADS, hh = i - node * HEADS;
    const float* row = h + (size_t)node * C1 + hh * HID;
    __nv_bfloat16* brow = hb + (size_t)node * C1 + hh * HID;
    const float* ws = att_s + hh * HID;
    const float* wd = att_d + hh * HID;
    float s = 0.f, d = 0.f;
    #pragma unroll
    for (int f = 0; f < HID; f += 2) {
        float v0 = row[f], v1 = row[f+1];
        s = fmaf(v0, ws[f], s); d = fmaf(v0, wd[f], d);
        s = fmaf(v1, ws[f+1], s); d = fmaf(v1, wd[f+1], d);
        *(__nv_bfloat162*)(brow + f) = __floats2bfloat162_rn(v0, v1);
    }
    as[i] = s;
    ad[i] = d;
}

__global__ void attn_coeff2(const float* __restrict__ h,
                            const float* __restrict__ att_s,
                            const float* __restrict__ att_d,
                            float* __restrict__ as, float* __restrict__ ad, int n) {
    int i = blockIdx.x * blockDim.x + threadIdx.x;
    if (i >= n) return;
    const float* row = h + (size_t)i * OUT_CH;
    float s = 0.f, d = 0.f;
    #pragma unroll 8
    for (int f = 0; f < OUT_CH; f++) {
        float v = row[f];
        s = fmaf(v, att_s[f], s);
        d = fmaf(v, att_d[f], d);
    }
    as[i] = s;
    ad[i] = d;
}

// ---------------- fused per-node softmax + aggregation, layer 1 -------------
__global__ void node_l1(const int* __restrict__ rowptr, const int* __restrict__ csrc,
                        const float* __restrict__ as, const float* __restrict__ ad,
                        const __nv_bfloat16* __restrict__ hb,
                        const float* __restrict__ bias,
                        float* __restrict__ out, int n) {
    __shared__ float buf[8][8][CAP];
    int w = threadIdx.x >> 5, lane = threadIdx.x & 31;
    int node = blockIdx.x * 8 + w;
    if (node >= n) return;
    int r0 = rowptr[node];
    int deg = rowptr[node+1] - r0;
    int g = lane >> 2, li = lane & 3;
    float ad_h = ad[node*8 + g];

    float mymax = -FLT_MAX;
    for (int k = li; k < deg; k += 4) {
        int s = csrc[r0 + k];
        float e = as[s*8 + g] + ad_h;
        e = e > 0.f ? e : NEG_SLOPE * e;
        if (k < CAP) buf[w][g][k] = e;
        mymax = fmaxf(mymax, e);
    }
    mymax = fmaxf(mymax, __shfl_xor_sync(0xffffffffu, mymax, 1));
    mymax = fmaxf(mymax, __shfl_xor_sync(0xffffffffu, mymax, 2));
    __syncwarp();

    float sum = 0.f;
    for (int k = li; k < deg; k += 4) {
        float e;
        if (k < CAP) e = buf[w][g][k];
        else {
            int s = csrc[r0 + k];
            e = as[s*8 + g] + ad_h;
            e = e > 0.f ? e : NEG_SLOPE * e;
        }
        float x = __expf(e - mymax);
        if (k < CAP) buf[w][g][k] = x;
        sum += x;
    }
    sum += __shfl_xor_sync(0xffffffffu, sum, 1);
    sum += __shfl_xor_sync(0xffffffffu, sum, 2);
    float invden = 1.f / sum;
    __syncwarp();

    float acc[8] = {};
    for (int base = 0; base < deg; base += 32) {
        int myS = (base + lane < deg) ? csrc[r0 + base + lane] : 0;
        int kmax = min(32, deg - base);
        int kk = 0;
        for (; kk + 1 < kmax; kk += 2) {
            int k0i = base + kk, k1i = base + kk + 1;
            int s0 = __shfl_sync(0xffffffffu, myS, kk);
            int s1 = __shfl_sync(0xffffffffu, myS, kk + 1);
            uint4 r0v = *(const uint4*)(hb + (size_t)s0*C1 + lane*8);
            uint4 r1v = *(const uint4*)(hb + (size_t)s1*C1 + lane*8);
            float a0, a1;
            if (k0i < CAP) a0 = buf[w][g][k0i] * invden;
            else {
                float e = as[s0*8 + g] + ad_h;
                e = e > 0.f ? e : NEG_SLOPE * e;
                a0 = __expf(e - mymax) * invden;
            }
            if (k1i < CAP) a1 = buf[w][g][k1i] * invden;
            else {
                float e = as[s1*8 + g] + ad_h;
                e = e > 0.f ? e : NEG_SLOPE * e;
                a1 = __expf(e - mymax) * invden;
            }
            const unsigned* u0 = &r0v.x;
            const unsigned* u1 = &r1v.x;
            #pragma unroll
            for (int q = 0; q < 4; q++) {
                float2 f0 = __bfloat1622float2(*(const __nv_bfloat162*)&u0[q]);
                float2 f1 = __bfloat1622float2(*(const __nv_bfloat162*)&u1[q]);
                acc[q*2+0] = fmaf(a0, f0.x, acc[q*2+0]);
                acc[q*2+1] = fmaf(a0, f0.y, acc[q*2+1]);
                acc[q*2+0] = fmaf(a1, f1.x, acc[q*2+0]);
                acc[q*2+1] = fmaf(a1, f1.y, acc[q*2+1]);
            }
        }
        if (kk < kmax) {
            int ki = base + kk;
            int s = __shfl_sync(0xffffffffu, myS, kk);
            uint4 rv = *(const uint4*)(hb + (size_t)s*C1 + lane*8);
            float a;
            if (ki < CAP) a = buf[w][g][ki] * invden;
            else {
                float e = as[s*8 + g] + ad_h;
                e = e > 0.f ? e : NEG_SLOPE * e;
                a = __expf(e - mymax) * invden;
            }
            const unsigned* u = &rv.x;
            #pragma unroll
            for (int q = 0; q < 4; q++) {
                float2 f = __bfloat1622float2(*(const __nv_bfloat162*)&u[q]);
                acc[q*2+0] = fmaf(a, f.x, acc[q*2+0]);
                acc[q*2+1] = fmaf(a, f.y, acc[q*2+1]);
            }
        }
    }
    float4 o0, o1;
    const float4* bp = (const float4*)(bias + lane*8);
    float4 b0 = bp[0], b1 = bp[1];
    o0.x = fmaxf(acc[0] + b0.x, 0.f); o0.y = fmaxf(acc[1] + b0.y, 0.f);
    o0.z = fmaxf(acc[2] + b0.z, 0.f); o0.w = fmaxf(acc[3] + b0.w, 0.f);
    o1.x = fmaxf(acc[4] + b1.x, 0.f); o1.y = fmaxf(acc[5] + b1.y, 0.f);
    o1.z = fmaxf(acc[6] + b1.z, 0.f); o1.w = fmaxf(acc[7] + b1.w, 0.f);
    float4* op = (float4*)(out + (size_t)node*C1 + lane*8);
    op[0] = o0; op[1] = o1;
}

// ---------------- fused per-node softmax + aggregation, layer 2 -------------
__global__ void node_l2(const int* __restrict__ rowptr, const int* __restrict__ csrc,
                        const float* __restrict__ as, const float* __restrict__ ad,
                        const float* __restrict__ h, const float* __restrict__ bias,
                        float* __restrict__ out, int n) {
    __shared__ float buf[8][CAP];
    int w = threadIdx.x >> 5, lane = threadIdx.x & 31;
    int node = blockIdx.x * 8 + w;
    if (node >= n) return;
    int r0 = rowptr[node];
    int deg = rowptr[node+1] - r0;
    float ad_h = ad[node];

    float mymax = -FLT_MAX;
    for (int k = lane; k < deg; k += 32) {
        int s = csrc[r0 + k];
        float e = as[s] + ad_h;
        e = e > 0.f ? e : NEG_SLOPE * e;
        if (k < CAP) buf[w][k] = e;
        mymax = fmaxf(mymax, e);
    }
    #pragma unroll
    for (int m = 1; m < 32; m <<= 1)
        mymax = fmaxf(mymax, __shfl_xor_sync(0xffffffffu, mymax, m));
    __syncwarp();

    float sum = 0.f;
    for (int k = lane; k < deg; k += 32) {
        float e;
        if (k < CAP) e = buf[w][k];
        else {
            int s = csrc[r0 + k];
            e = as[s] + ad_h;
            e = e > 0.f ? e : NEG_SLOPE * e;
        }
        float x = __expf(e - mymax);
        if (k < CAP) buf[w][k] = x;
        sum += x;
    }
    #pragma unroll
    for (int m = 1; m < 32; m <<= 1)
        sum += __shfl_xor_sync(0xffffffffu, sum, m);
    float invden = 1.f / sum;
    __syncwarp();

    float2 acc = make_float2(0.f, 0.f);
    for (int base = 0; base < deg; base += 32) {
        int myS = (base + lane < deg) ? csrc[r0 + base + lane] : 0;
        int kmax = min(32, deg - base);
        int kk = 0;
        for (; kk + 1 < kmax; kk += 2) {
            int k0i = base + kk, k1i = base + kk + 1;
            int s0 = __shfl_sync(0xffffffffu, myS, kk);
            int s1 = __shfl_sync(0xffffffffu, myS, kk + 1);
            float2 v0 = *(const float2*)(h + (size_t)s0*OUT_CH + lane*2);
            float2 v1 = *(const float2*)(h + (size_t)s1*OUT_CH + lane*2);
            float a0, a1;
            if (k0i < CAP) a0 = buf[w][k0i] * invden;
            else {
                float e = as[s0] + ad_h;
                e = e > 0.f ? e : NEG_SLOPE * e;
                a0 = __expf(e - mymax) * invden;
            }
            if (k1i < CAP) a1 = buf[w][k1i] * invden;
            else {
                float e = as[s1] + ad_h;
                e = e > 0.f ? e : NEG_SLOPE * e;
                a1 = __expf(e - mymax) * invden;
            }
            acc.x = fmaf(a0, v0.x, acc.x); acc.y = fmaf(a0, v0.y, acc.y);
            acc.x = fmaf(a1, v1.x, acc.x); acc.y = fmaf(a1, v1.y, acc.y);
        }
        if (kk < kmax) {
            int ki = base + kk;
            int s = __shfl_sync(0xffffffffu, myS, kk);
            float2 v = *(const float2*)(h + (size_t)s*OUT_CH + lane*2);
            float a;
            if (ki < CAP) a = buf[w][ki] * invden;
            else {
                float e = as[s] + ad_h;
                e = e > 0.f ? e : NEG_SLOPE * e;
                a = __expf(e - mymax) * invden;
            }
            acc.x = fmaf(a, v.x, acc.x); acc.y = fmaf(a, v.y, acc.y);
        }
    }
    acc.x += bias[lane*2];
    acc.y += bias[lane*2+1];
    *(float2*)(out + (size_t)node*OUT_CH + lane*2) = acc;
}

// ---------------- launch ----------------------------------------------------
extern "C" void kernel_launch(void* const* d_in, const int* in_sizes, int n_in,
                              void* d_out, int out_size) {
    const float* x      = (const float*)d_in[0];
    const int*   ei     = (const int*)d_in[1];
    const float* W1     = (const float*)d_in[2];
    const float* att_s1 = (const float*)d_in[3];
    const float* att_d1 = (const float*)d_in[4];
    const float* b1     = (const float*)d_in[5];
    const float* W2     = (const float*)d_in[6];
    const float* att_s2 = (const float*)d_in[7];
    const float* att_d2 = (const float*)d_in[8];
    const float* b2     = (const float*)d_in[9];
    float* out = (float*)d_out;

    int n    = in_sizes[0] / IN_CH;   // 50000
    int E    = in_sizes[1] / 2;       // 800000
    int Etot = E + n;
    const int* src = ei;
    const int* dst = ei + E;

    float *h1, *o1, *h2, *as1, *ad1, *as2, *ad2;
    __nv_bfloat16* h1b;
    int *deg, *rowptr, *cursor, *csrc, *bsums;
    cudaGetSymbolAddress((void**)&h1,     g_h1);
    cudaGetSymbolAddress((void**)&h1b,    g_h1b);
    cudaGetSymbolAddress((void**)&o1,     g_o1);
    cudaGetSymbolAddress((void**)&h2,     g_h2);
    cudaGetSymbolAddress((void**)&as1,    g_as1);
    cudaGetSymbolAddress((void**)&ad1,    g_ad1);
    cudaGetSymbolAddress((void**)&as2,    g_as2);
    cudaGetSymbolAddress((void**)&ad2,    g_ad2);
    cudaGetSymbolAddress((void**)&deg,    g_deg);
    cudaGetSymbolAddress((void**)&rowptr, g_rowptr);
    cudaGetSymbolAddress((void**)&cursor, g_cursor);
    cudaGetSymbolAddress((void**)&csrc,   g_csrc);
    cudaGetSymbolAddress((void**)&bsums,  g_bsums);

    int nb = (n + 1023) / 1024;

    // ---- CSR build ----
    fill_int_k<<<(n + 255)/256, 256>>>(deg, 1, n);   // self-loop baked in
    hist_k<<<(E + 255)/256, 256>>>(dst, deg, E);
    bscan_k<<<nb, 1024>>>(deg, rowptr, bsums, n);
    pscan_k<<<1, 64>>>(bsums, nb);
    addoff_k<<<(n + 255)/256, 256>>>(rowptr, cursor, bsums, n);
    scatter_k<<<(Etot + 255)/256, 256>>>(src, dst, cursor, csrc, Etot, E);

    // ---- layer 1 ----
    {
        dim3 grid(C1/128, (n + 127)/128);
        gemm_tf32<128><<<grid, 256>>>(x, W1, h1, n, C1, IN_CH);
    }
    attn1_fused<<<(n*HEADS + 255)/256, 256>>>(h1, att_s1, att_d1, as1, ad1, h1b, n);
    node_l1<<<(n + 7)/8, 256>>>(rowptr, csrc, as1, ad1, h1b, b1, o1, n);

    // ---- layer 2 ----
    {
        dim3 grid(OUT_CH/64, (n + 127)/128);
        gemm_tf32<64><<<grid, 256>>>(o1, W2, h2, n, OUT_CH, C1);
    }
    attn_coeff2<<<(n + 255)/256, 256>>>(h2, att_s2, att_d2, as2, ad2, n);
    node_l2<<<(n + 7)/8, 256>>>(rowptr, csrc, as2, ad2, h2, b2, out, n);
}